// round 7
// baseline (speedup 1.0000x reference)
#include <cuda_runtime.h>
#include <math.h>
#include <stdint.h>

// Problem constants
#define D_MODEL 1024
#define N_HEADS 16
#define DKH     64
#define BATCH   2
#define SEQ     2048
#define M_TOT   (BATCH * SEQ)   // 4096

// ---------------- scratch ----------------------------------------------------
__device__ float g_Q[M_TOT * D_MODEL];
__device__ float g_K[M_TOT * D_MODEL];
__device__ float g_V[M_TOT * D_MODEL];
__device__ float g_A[M_TOT * D_MODEL];

// ---------------- helpers ----------------------------------------------------
__device__ __forceinline__ unsigned f2tf(float f) {
    unsigned r;
    asm("cvt.rna.tf32.f32 %0, %1;" : "=r"(r) : "f"(f));
    return r;
}

__device__ __forceinline__ uint32_t s2u(const void* p) {
    uint32_t a;
    asm("{ .reg .u64 t; cvta.to.shared.u64 t, %1; cvt.u32.u64 %0, t; }"
        : "=r"(a) : "l"(p));
    return a;
}

__device__ __forceinline__ void cpa16(uint32_t s, const void* g) {
    asm volatile("cp.async.cg.shared.global [%0], [%1], 16;" :: "r"(s), "l"(g));
}

__device__ __forceinline__ void mma_tf32(float* c, const unsigned* a, const unsigned* b) {
    asm volatile(
        "mma.sync.aligned.m16n8k8.row.col.f32.tf32.tf32.f32 "
        "{%0,%1,%2,%3}, {%4,%5,%6,%7}, {%8,%9}, {%0,%1,%2,%3};"
        : "+f"(c[0]), "+f"(c[1]), "+f"(c[2]), "+f"(c[3])
        : "r"(a[0]), "r"(a[1]), "r"(a[2]), "r"(a[3]), "r"(b[0]), "r"(b[1]));
}

// ---------------- GEMM: Y = X[M,K] * W[N,K]^T + bias -------------------------
// 256 thr / 8 warps, CTA tile 128x128, BK=32.  cp.async double-buffered raw
// fp32 staging; tf32 cvt at fragment-load time.  Warp tile 64x32.
#define GSTR      36                      // 36 % 32 == 4 -> conflict-free frags
#define GEMM_NCH  (D_MODEL / 32)          // 32 chunks
#define GEMM_BUF  (128 * GSTR)            // floats per operand buffer
#define GEMM_SMEM (4 * GEMM_BUF * 4)      // 73728 B

__global__ __launch_bounds__(256, 2)
void gemm_cp_kernel(const float* __restrict__ X, const float* __restrict__ W,
                    const float* __restrict__ bias, float* __restrict__ Y,
                    int M, int N, int K)
{
    extern __shared__ float smem[];
    float* Xb[2] = { smem,                smem + GEMM_BUF };
    float* Wb[2] = { smem + 2 * GEMM_BUF, smem + 3 * GEMM_BUF };

    const int tid  = threadIdx.x;
    const int warp = tid >> 5, lane = tid & 31;
    const int wm = warp >> 2, wn = warp & 3;
    const int g  = lane >> 2, tg = lane & 3;
    const int bm = blockIdx.y * 128, bn = blockIdx.x * 128;

    const int lr = tid >> 3;         // 0..31
    const int lc = (tid & 7) * 4;    // 0..28

    const float* xg = X + (size_t)(bm + lr) * K + lc;
    const float* wg = W + (size_t)(bn + lr) * K + lc;
    const uint32_t sx[2] = { s2u(Xb[0] + lr * GSTR + lc), s2u(Xb[1] + lr * GSTR + lc) };
    const uint32_t sw[2] = { s2u(Wb[0] + lr * GSTR + lc), s2u(Wb[1] + lr * GSTR + lc) };

    float c[4][4][4];
#pragma unroll
    for (int mf = 0; mf < 4; mf++)
#pragma unroll
        for (int nf = 0; nf < 4; nf++)
#pragma unroll
            for (int k = 0; k < 4; k++) c[mf][nf][k] = 0.f;

    // issue staging for chunk ch into buffer buf
    auto issue = [&](int ch, int buf) {
        const float* xp = xg + ch * 32;
        const float* wp = wg + ch * 32;
#pragma unroll
        for (int i = 0; i < 4; i++) {
            cpa16(sx[buf] + (uint32_t)(i * 32 * GSTR * 4), xp + (size_t)(i * 32) * K);
            cpa16(sw[buf] + (uint32_t)(i * 32 * GSTR * 4), wp + (size_t)(i * 32) * K);
        }
        asm volatile("cp.async.commit_group;" ::: "memory");
    };

    issue(0, 0);

    for (int ch = 0; ch < GEMM_NCH; ch++) {
        const int buf = ch & 1;
        if (ch + 1 < GEMM_NCH) {
            issue(ch + 1, buf ^ 1);
            asm volatile("cp.async.wait_group 1;" ::: "memory");
        } else {
            asm volatile("cp.async.wait_group 0;" ::: "memory");
        }
        __syncthreads();

        const float* Xs = Xb[buf];
        const float* Ws = Wb[buf];
#pragma unroll
        for (int ks = 0; ks < 4; ks++) {
            unsigned a[4][4], b[4][2];
#pragma unroll
            for (int mf = 0; mf < 4; mf++) {
                int row = wm * 64 + mf * 16;
                a[mf][0] = f2tf(Xs[(row + g    ) * GSTR + ks * 8 + tg    ]);
                a[mf][1] = f2tf(Xs[(row + g + 8) * GSTR + ks * 8 + tg    ]);
                a[mf][2] = f2tf(Xs[(row + g    ) * GSTR + ks * 8 + tg + 4]);
                a[mf][3] = f2tf(Xs[(row + g + 8) * GSTR + ks * 8 + tg + 4]);
            }
#pragma unroll
            for (int nf = 0; nf < 4; nf++) {
                int col = wn * 32 + nf * 8 + g;
                b[nf][0] = f2tf(Ws[col * GSTR + ks * 8 + tg    ]);
                b[nf][1] = f2tf(Ws[col * GSTR + ks * 8 + tg + 4]);
            }
#pragma unroll
            for (int mf = 0; mf < 4; mf++)
#pragma unroll
                for (int nf = 0; nf < 4; nf++)
                    mma_tf32(c[mf][nf], a[mf], b[nf]);
        }
        __syncthreads();
    }

    // epilogue: bias + store
#pragma unroll
    for (int mf = 0; mf < 4; mf++) {
#pragma unroll
        for (int nf = 0; nf < 4; nf++) {
            int row = bm + wm * 64 + mf * 16 + g;
            int col = bn + wn * 32 + nf * 8 + 2 * tg;
            float b0 = bias[col], b1 = bias[col + 1];
            *(float2*)(Y + (size_t)row * N + col) =
                make_float2(c[mf][nf][0] + b0, c[mf][nf][1] + b1);
            *(float2*)(Y + (size_t)(row + 8) * N + col) =
                make_float2(c[mf][nf][2] + b0, c[mf][nf][3] + b1);
        }
    }
}

// ---------------- flash attention, tf32 mma, BQ=128 --------------------------
// 256 thr / 8 warps, 128 q-rows per block (16 per warp), KV tiles of 64.
// Pair layout (word pairs (k, k+4)) for Ks and P -> fragment LDS.64.
// Layout word addr: PADDR(r,c) = r*72 + (c>>3)*8 + ((c&7)<4 ? (c&3)*2 : (c&3)*2+1)
#define FSTR 72   // 72/2 = 36 == 4 (mod 16) -> conflict-free LDS.64
#define FLASH_SMEM ((128 * FSTR + 64 * FSTR + 64 * FSTR) * 4)   // 73728 B

__global__ __launch_bounds__(256)
void flash_tf32_kernel()
{
    extern __shared__ unsigned fsm[];
    unsigned* Ps = fsm;                    // [128][FSTR] pair layout (Q staging, then P)
    unsigned* Ks = Ps + 128 * FSTR;        // [64][FSTR]  pair layout
    unsigned* Vs = Ks + 64 * FSTR;         // [64][FSTR]  row-major (k rows, d cols)

    const int tid  = threadIdx.x;
    const int warp = tid >> 5, lane = tid & 31;
    const int g = lane >> 2, tg = lane & 3;
    const int qt = (int)gridDim.x - 1 - (int)blockIdx.x;   // reversed: heavy first
    const int bh = blockIdx.y;
    const int b  = bh >> 4, h = bh & 15;
    const int qbase = qt * 128;
    const int row0  = warp * 16;

    const size_t base = (size_t)b * SEQ * D_MODEL + (size_t)h * DKH;
    const float* Qg = g_Q + base;
    const float* Kg = g_K + base;
    const float* Vg = g_V + base;

    // ---- stage Q (128x64) into Ps pair layout ----
#pragma unroll
    for (int i = 0; i < 8; i++) {
        int idx = tid + i * 256;           // 0..2047 float4s
        int r = idx >> 4, q = idx & 15;
        float4 v = *(const float4*)(Qg + (size_t)(qbase + r) * D_MODEL + q * 4);
        unsigned bo = r * FSTR + (q >> 1) * 8 + (q & 1);
        Ps[bo + 0] = f2tf(v.x); Ps[bo + 2] = f2tf(v.y);
        Ps[bo + 4] = f2tf(v.z); Ps[bo + 6] = f2tf(v.w);
    }
    __syncthreads();

    // ---- extract Q fragments (warp's 16 rows) ----
    unsigned qf[8][4];
#pragma unroll
    for (int ks = 0; ks < 8; ks++) {
        uint2 t0 = *(const uint2*)&Ps[(row0 + g    ) * FSTR + ks * 8 + tg * 2];
        uint2 t1 = *(const uint2*)&Ps[(row0 + g + 8) * FSTR + ks * 8 + tg * 2];
        qf[ks][0] = t0.x; qf[ks][2] = t0.y;
        qf[ks][1] = t1.x; qf[ks][3] = t1.y;
    }

    float O[8][4];
#pragma unroll
    for (int nf = 0; nf < 8; nf++)
#pragma unroll
        for (int k = 0; k < 4; k++) O[nf][k] = 0.f;
    float m0 = -1e30f, m1 = -1e30f, l0 = 0.f, l1 = 0.f;

    const int q0 = qbase + row0 + g;
    const int q1 = q0 + 8;
    const int qmaxw = qbase + row0 + 15;        // warp's last q row

    const int nkt = 2 * qt + 2;
    for (int kt = 0; kt < nkt; kt++) {
        const int kbase = kt * 64;
        __syncthreads();
        // ---- stage K (pair layout) and V (row-major, STS.128) ----
#pragma unroll
        for (int i = 0; i < 4; i++) {
            int idx = tid + i * 256;       // 0..1023 float4s
            int r = idx >> 4, q = idx & 15;
            float4 kv = *(const float4*)(Kg + (size_t)(kbase + r) * D_MODEL + q * 4);
            float4 vv = *(const float4*)(Vg + (size_t)(kbase + r) * D_MODEL + q * 4);
            unsigned bo = r * FSTR + (q >> 1) * 8 + (q & 1);
            Ks[bo + 0] = f2tf(kv.x); Ks[bo + 2] = f2tf(kv.y);
            Ks[bo + 4] = f2tf(kv.z); Ks[bo + 6] = f2tf(kv.w);
            *(uint4*)&Vs[r * FSTR + q * 4] =
                make_uint4(f2tf(vv.x), f2tf(vv.y), f2tf(vv.z), f2tf(vv.w));
        }
        __syncthreads();

        if (kbase > qmaxw) continue;       // fully-masked tile for this warp

        // ---- S = Q K^T  (m16 x n64), LDS.64 B-fragments ----
        float S[8][4];
#pragma unroll
        for (int nf = 0; nf < 8; nf++)
#pragma unroll
            for (int k = 0; k < 4; k++) S[nf][k] = 0.f;

#pragma unroll
        for (int ks = 0; ks < 8; ks++) {
#pragma unroll
            for (int nf = 0; nf < 8; nf++) {
                uint2 bv = *(const uint2*)&Ks[(nf * 8 + g) * FSTR + ks * 8 + tg * 2];
                unsigned bb[2] = { bv.x, bv.y };
                mma_tf32(S[nf], qf[ks], bb);
            }
        }

        // ---- scale + causal mask ----
        const bool diag = (kbase + 63 > q0);
#pragma unroll
        for (int nf = 0; nf < 8; nf++) {
            int kc0 = kbase + nf * 8 + 2 * tg;
            S[nf][0] *= 0.125f; S[nf][1] *= 0.125f;
            S[nf][2] *= 0.125f; S[nf][3] *= 0.125f;
            if (diag) {
                if (kc0     > q0) S[nf][0] = -1e30f;
                if (kc0 + 1 > q0) S[nf][1] = -1e30f;
                if (kc0     > q1) S[nf][2] = -1e30f;
                if (kc0 + 1 > q1) S[nf][3] = -1e30f;
            }
        }

        // ---- online softmax ----
        float mx0 = -1e30f, mx1 = -1e30f;
#pragma unroll
        for (int nf = 0; nf < 8; nf++) {
            mx0 = fmaxf(mx0, fmaxf(S[nf][0], S[nf][1]));
            mx1 = fmaxf(mx1, fmaxf(S[nf][2], S[nf][3]));
        }
        mx0 = fmaxf(mx0, __shfl_xor_sync(0xffffffffu, mx0, 1));
        mx0 = fmaxf(mx0, __shfl_xor_sync(0xffffffffu, mx0, 2));
        mx1 = fmaxf(mx1, __shfl_xor_sync(0xffffffffu, mx1, 1));
        mx1 = fmaxf(mx1, __shfl_xor_sync(0xffffffffu, mx1, 2));

        float mn0 = fmaxf(m0, mx0), mn1 = fmaxf(m1, mx1);
        float fac0 = __expf(m0 - mn0), fac1 = __expf(m1 - mn1);

        float s0 = 0.f, s1 = 0.f;
#pragma unroll
        for (int nf = 0; nf < 8; nf++) {
            S[nf][0] = __expf(S[nf][0] - mn0);
            S[nf][1] = __expf(S[nf][1] - mn0);
            S[nf][2] = __expf(S[nf][2] - mn1);
            S[nf][3] = __expf(S[nf][3] - mn1);
            s0 += S[nf][0] + S[nf][1];
            s1 += S[nf][2] + S[nf][3];
        }
        s0 += __shfl_xor_sync(0xffffffffu, s0, 1);
        s0 += __shfl_xor_sync(0xffffffffu, s0, 2);
        s1 += __shfl_xor_sync(0xffffffffu, s1, 1);
        s1 += __shfl_xor_sync(0xffffffffu, s1, 2);

        l0 = l0 * fac0 + s0; l1 = l1 * fac1 + s1;
        m0 = mn0; m1 = mn1;
#pragma unroll
        for (int nf = 0; nf < 8; nf++) {
            O[nf][0] *= fac0; O[nf][1] *= fac0;
            O[nf][2] *= fac1; O[nf][3] *= fac1;
        }

        // ---- P -> smem in pair layout (per-warp rows) ----
        {
            const int off0 = (tg < 2) ? 4 * tg : 4 * tg - 7;
#pragma unroll
            for (int nf = 0; nf < 8; nf++) {
                unsigned w0 = (row0 + g    ) * FSTR + nf * 8 + off0;
                unsigned w1 = (row0 + g + 8) * FSTR + nf * 8 + off0;
                Ps[w0    ] = f2tf(S[nf][0]);
                Ps[w0 + 2] = f2tf(S[nf][1]);
                Ps[w1    ] = f2tf(S[nf][2]);
                Ps[w1 + 2] = f2tf(S[nf][3]);
            }
        }
        __syncwarp();

        // ---- O += P V ----
#pragma unroll
        for (int ks = 0; ks < 8; ks++) {
            uint2 t0 = *(const uint2*)&Ps[(row0 + g    ) * FSTR + ks * 8 + tg * 2];
            uint2 t1 = *(const uint2*)&Ps[(row0 + g + 8) * FSTR + ks * 8 + tg * 2];
            unsigned a[4] = { t0.x, t1.x, t0.y, t1.y };
#pragma unroll
            for (int nf = 0; nf < 8; nf++) {
                unsigned bb[2];
                bb[0] = Vs[(ks * 8 + tg    ) * FSTR + nf * 8 + g];
                bb[1] = Vs[(ks * 8 + tg + 4) * FSTR + nf * 8 + g];
                mma_tf32(O[nf], a, bb);
            }
        }
        __syncwarp();
    }

    // ---- normalize + write ----
    float inv0 = 1.0f / l0, inv1 = 1.0f / l1;
    float* Ag = g_A + base;
#pragma unroll
    for (int nf = 0; nf < 8; nf++) {
        int col = nf * 8 + 2 * tg;
        *(float2*)(Ag + (size_t)q0 * D_MODEL + col) =
            make_float2(O[nf][0] * inv0, O[nf][1] * inv0);
        *(float2*)(Ag + (size_t)q1 * D_MODEL + col) =
            make_float2(O[nf][2] * inv1, O[nf][3] * inv1);
    }
}

// ---------------- launch -----------------------------------------------------
extern "C" void kernel_launch(void* const* d_in, const int* in_sizes, int n_in,
                              void* d_out, int out_size)
{
    (void)in_sizes; (void)n_in; (void)out_size;
    const float* in_Q = (const float*)d_in[0];
    const float* in_K = (const float*)d_in[1];
    const float* in_V = (const float*)d_in[2];
    const float* Wq   = (const float*)d_in[3];
    const float* bq   = (const float*)d_in[4];
    const float* Wk   = (const float*)d_in[5];
    const float* bk   = (const float*)d_in[6];
    const float* Wv   = (const float*)d_in[7];
    const float* bv   = (const float*)d_in[8];
    const float* Wo   = (const float*)d_in[9];
    const float* bo   = (const float*)d_in[10];
    float* out = (float*)d_out;

    float *qp, *kp, *vp, *ap;
    cudaGetSymbolAddress((void**)&qp, g_Q);
    cudaGetSymbolAddress((void**)&kp, g_K);
    cudaGetSymbolAddress((void**)&vp, g_V);
    cudaGetSymbolAddress((void**)&ap, g_A);

    cudaFuncSetAttribute(gemm_cp_kernel,
                         cudaFuncAttributeMaxDynamicSharedMemorySize, GEMM_SMEM);
    cudaFuncSetAttribute(flash_tf32_kernel,
                         cudaFuncAttributeMaxDynamicSharedMemorySize, FLASH_SMEM);

    dim3 gemm_grid(D_MODEL / 128, M_TOT / 128);   // (8, 32)

    gemm_cp_kernel<<<gemm_grid, 256, GEMM_SMEM>>>(in_Q, Wq, bq, qp, M_TOT, D_MODEL, D_MODEL);
    gemm_cp_kernel<<<gemm_grid, 256, GEMM_SMEM>>>(in_K, Wk, bk, kp, M_TOT, D_MODEL, D_MODEL);
    gemm_cp_kernel<<<gemm_grid, 256, GEMM_SMEM>>>(in_V, Wv, bv, vp, M_TOT, D_MODEL, D_MODEL);

    dim3 fgrid(SEQ / 128, BATCH * N_HEADS);       // (16, 32)
    flash_tf32_kernel<<<fgrid, 256, FLASH_SMEM>>>();

    gemm_cp_kernel<<<gemm_grid, 256, GEMM_SMEM>>>(ap, Wo, bo, out, M_TOT, D_MODEL, D_MODEL);
}

// round 8
// speedup vs baseline: 1.0275x; 1.0275x over previous
#include <cuda_runtime.h>
#include <math.h>
#include <stdint.h>

// Problem constants
#define D_MODEL 1024
#define N_HEADS 16
#define DKH     64
#define BATCH   2
#define SEQ     2048
#define M_TOT   (BATCH * SEQ)   // 4096

// ---------------- scratch ----------------------------------------------------
__device__ float g_Q[M_TOT * D_MODEL];
__device__ float g_K[M_TOT * D_MODEL];
__device__ float g_V[M_TOT * D_MODEL];
__device__ float g_A[M_TOT * D_MODEL];

// ---------------- helpers ----------------------------------------------------
__device__ __forceinline__ unsigned f2tf(float f) {
    unsigned r;
    asm("cvt.rna.tf32.f32 %0, %1;" : "=r"(r) : "f"(f));
    return r;
}

__device__ __forceinline__ void mma_tf32(float* c, const unsigned* a, const unsigned* b) {
    asm volatile(
        "mma.sync.aligned.m16n8k8.row.col.f32.tf32.tf32.f32 "
        "{%0,%1,%2,%3}, {%4,%5,%6,%7}, {%8,%9}, {%0,%1,%2,%3};"
        : "+f"(c[0]), "+f"(c[1]), "+f"(c[2]), "+f"(c[3])
        : "r"(a[0]), "r"(a[1]), "r"(a[2]), "r"(a[3]), "r"(b[0]), "r"(b[1]));
}

// ---------------- GEMM: Y = X[M,K] * W[N,K]^T + bias -------------------------
// 256 thr / 8 warps, CTA tile 128x128, BK=32, warp tile 64x32.
// Double-buffered smem; register prefetch of chunk c+1 overlapped with MMA of c.
// cvt.tf32 happens ONCE per element, in staging.
#define GSTR      36                        // 36 % 32 == 4 -> conflict-free frags
#define GEMM_NCH  (D_MODEL / 32)            // 32 chunks
#define GEMM_BUF  (128 * GSTR)              // words per operand buffer
#define GEMM_SMEM (4 * GEMM_BUF * 4)        // 73728 B

__device__ __forceinline__ void gemm_body(
    const float* __restrict__ X, const float* __restrict__ W,
    const float* __restrict__ bias, float* __restrict__ Y,
    unsigned* smem)
{
    const int M = M_TOT, N = D_MODEL, K = D_MODEL;
    (void)M;

    unsigned* Xb[2] = { smem,                smem + GEMM_BUF };
    unsigned* Wb[2] = { smem + 2 * GEMM_BUF, smem + 3 * GEMM_BUF };

    const int tid  = threadIdx.x;
    const int warp = tid >> 5, lane = tid & 31;
    const int wm = warp >> 2, wn = warp & 3;
    const int g  = lane >> 2, tg = lane & 3;
    const int bm = blockIdx.y * 128, bn = blockIdx.x * 128;

    const int lr = tid >> 3;         // 0..31
    const int lc = (tid & 7) * 4;    // 0..28

    const float* xg = X + (size_t)(bm + lr) * K + lc;
    const float* wg = W + (size_t)(bn + lr) * K + lc;

    float c[4][4][4];
#pragma unroll
    for (int mf = 0; mf < 4; mf++)
#pragma unroll
        for (int nf = 0; nf < 4; nf++)
#pragma unroll
            for (int k = 0; k < 4; k++) c[mf][nf][k] = 0.f;

    float4 px[4], pw[4];

    auto ldg = [&](int ch) {
        const float* xp = xg + ch * 32;
        const float* wp = wg + ch * 32;
#pragma unroll
        for (int i = 0; i < 4; i++) {
            px[i] = *(const float4*)(xp + (size_t)(i * 32) * K);
            pw[i] = *(const float4*)(wp + (size_t)(i * 32) * K);
        }
    };

    auto sts = [&](int buf) {
        unsigned* Xs = Xb[buf];
        unsigned* Ws = Wb[buf];
#pragma unroll
        for (int i = 0; i < 4; i++) {
            int r = lr + 32 * i;
            *(uint4*)&Xs[r * GSTR + lc] =
                make_uint4(f2tf(px[i].x), f2tf(px[i].y), f2tf(px[i].z), f2tf(px[i].w));
            *(uint4*)&Ws[r * GSTR + lc] =
                make_uint4(f2tf(pw[i].x), f2tf(pw[i].y), f2tf(pw[i].z), f2tf(pw[i].w));
        }
    };

    ldg(0);
    sts(0);
    __syncthreads();

    for (int ch = 0; ch < GEMM_NCH; ch++) {
        const int buf = ch & 1;
        if (ch + 1 < GEMM_NCH) ldg(ch + 1);   // prefetch overlaps the MMAs below

        const unsigned* Xs = Xb[buf];
        const unsigned* Ws = Wb[buf];
#pragma unroll
        for (int ks = 0; ks < 4; ks++) {
            unsigned a[4][4], b[4][2];
#pragma unroll
            for (int mf = 0; mf < 4; mf++) {
                int row = wm * 64 + mf * 16;
                a[mf][0] = Xs[(row + g    ) * GSTR + ks * 8 + tg    ];
                a[mf][1] = Xs[(row + g + 8) * GSTR + ks * 8 + tg    ];
                a[mf][2] = Xs[(row + g    ) * GSTR + ks * 8 + tg + 4];
                a[mf][3] = Xs[(row + g + 8) * GSTR + ks * 8 + tg + 4];
            }
#pragma unroll
            for (int nf = 0; nf < 4; nf++) {
                int col = wn * 32 + nf * 8 + g;
                b[nf][0] = Ws[col * GSTR + ks * 8 + tg    ];
                b[nf][1] = Ws[col * GSTR + ks * 8 + tg + 4];
            }
#pragma unroll
            for (int mf = 0; mf < 4; mf++)
#pragma unroll
                for (int nf = 0; nf < 4; nf++)
                    mma_tf32(c[mf][nf], a[mf], b[nf]);
        }

        if (ch + 1 < GEMM_NCH) sts(buf ^ 1);  // write other buffer
        __syncthreads();
    }

    // epilogue: bias + store
#pragma unroll
    for (int mf = 0; mf < 4; mf++) {
#pragma unroll
        for (int nf = 0; nf < 4; nf++) {
            int row = bm + wm * 64 + mf * 16 + g;
            int col = bn + wn * 32 + nf * 8 + 2 * tg;
            float b0 = bias[col], b1 = bias[col + 1];
            *(float2*)(Y + (size_t)row * N + col) =
                make_float2(c[mf][nf][0] + b0, c[mf][nf][1] + b1);
            *(float2*)(Y + (size_t)(row + 8) * N + col) =
                make_float2(c[mf][nf][2] + b0, c[mf][nf][3] + b1);
        }
    }
}

// Fused QKV projection: blockIdx.z selects (input, weight, bias, output).
__global__ __launch_bounds__(256)
void gemm_qkv_kernel(const float* __restrict__ X0, const float* __restrict__ X1,
                     const float* __restrict__ X2,
                     const float* __restrict__ W0, const float* __restrict__ W1,
                     const float* __restrict__ W2,
                     const float* __restrict__ b0, const float* __restrict__ b1,
                     const float* __restrict__ b2,
                     float* __restrict__ Y0, float* __restrict__ Y1,
                     float* __restrict__ Y2)
{
    extern __shared__ unsigned gsm[];
    const int z = blockIdx.z;
    const float* X = (z == 0) ? X0 : (z == 1) ? X1 : X2;
    const float* W = (z == 0) ? W0 : (z == 1) ? W1 : W2;
    const float* B = (z == 0) ? b0 : (z == 1) ? b1 : b2;
    float*       Y = (z == 0) ? Y0 : (z == 1) ? Y1 : Y2;
    gemm_body(X, W, B, Y, gsm);
}

__global__ __launch_bounds__(256)
void gemm_one_kernel(const float* __restrict__ X, const float* __restrict__ W,
                     const float* __restrict__ bias, float* __restrict__ Y)
{
    extern __shared__ unsigned gsm[];
    gemm_body(X, W, bias, Y, gsm);
}

// ---------------- flash attention, tf32 mma (R5 layout, BQ=64) ---------------
// 128 thr / 4 warps, 64 q-rows per block (16 per warp), KV tiles of 64.
#define PSTR 68   // g-indexed rows: 68 % 32 == 4
#define VSTR 72   // tg-indexed rows: 72 % 32 == 8
#define FLASH_SMEM ((64 * PSTR * 2 + 64 * VSTR) * 4)

__global__ __launch_bounds__(128)
void flash_tf32_kernel()
{
    extern __shared__ unsigned sm[];
    unsigned* Ps = sm;                   // [64][PSTR]  (Q staging, then P)
    unsigned* Ks = Ps + 64 * PSTR;       // [64][PSTR]
    unsigned* Vs = Ks + 64 * PSTR;       // [64][VSTR]

    const int tid  = threadIdx.x;
    const int warp = tid >> 5, lane = tid & 31;
    const int g = lane >> 2, tg = lane & 3;
    const int qt = (int)gridDim.x - 1 - (int)blockIdx.x;   // heavy blocks first
    const int bh = blockIdx.y;
    const int b  = bh >> 4, h = bh & 15;
    const int qbase = qt * 64;

    const size_t base = (size_t)b * SEQ * D_MODEL + (size_t)h * DKH;
    const float* Qg = g_Q + base;
    const float* Kg = g_K + base;
    const float* Vg = g_V + base;

    const int sr = tid >> 4;         // staging row 0..7
    const int sc = (tid & 15) * 4;   // staging col 0..60

    // ---- stage Q, extract Q fragments ----
#pragma unroll
    for (int p = 0; p < 8; p++) {
        int r = sr + 8 * p;
        float4 v = *(const float4*)(Qg + (size_t)(qbase + r) * D_MODEL + sc);
        Ps[r * PSTR + sc + 0] = f2tf(v.x); Ps[r * PSTR + sc + 1] = f2tf(v.y);
        Ps[r * PSTR + sc + 2] = f2tf(v.z); Ps[r * PSTR + sc + 3] = f2tf(v.w);
    }
    __syncthreads();

    unsigned qf[8][4];
    {
        int row = warp * 16;
#pragma unroll
        for (int ks = 0; ks < 8; ks++) {
            qf[ks][0] = Ps[(row + g    ) * PSTR + ks * 8 + tg    ];
            qf[ks][1] = Ps[(row + g + 8) * PSTR + ks * 8 + tg    ];
            qf[ks][2] = Ps[(row + g    ) * PSTR + ks * 8 + tg + 4];
            qf[ks][3] = Ps[(row + g + 8) * PSTR + ks * 8 + tg + 4];
        }
    }

    float O[8][4];
#pragma unroll
    for (int nf = 0; nf < 8; nf++)
#pragma unroll
        for (int k = 0; k < 4; k++) O[nf][k] = 0.f;
    float m0 = -1e30f, m1 = -1e30f, l0 = 0.f, l1 = 0.f;

    const int q0 = qbase + warp * 16 + g;
    const int q1 = q0 + 8;

    const int nkt = qt + 1;
    for (int kt = 0; kt < nkt; kt++) {
        const int kbase = kt * 64;
        __syncthreads();
#pragma unroll
        for (int p = 0; p < 8; p++) {
            int r = sr + 8 * p;
            float4 kv = *(const float4*)(Kg + (size_t)(kbase + r) * D_MODEL + sc);
            float4 vv = *(const float4*)(Vg + (size_t)(kbase + r) * D_MODEL + sc);
            Ks[r * PSTR + sc + 0] = f2tf(kv.x); Ks[r * PSTR + sc + 1] = f2tf(kv.y);
            Ks[r * PSTR + sc + 2] = f2tf(kv.z); Ks[r * PSTR + sc + 3] = f2tf(kv.w);
            Vs[r * VSTR + sc + 0] = f2tf(vv.x); Vs[r * VSTR + sc + 1] = f2tf(vv.y);
            Vs[r * VSTR + sc + 2] = f2tf(vv.z); Vs[r * VSTR + sc + 3] = f2tf(vv.w);
        }
        __syncthreads();

        // ---- S = Q K^T ----
        float S[8][4];
#pragma unroll
        for (int nf = 0; nf < 8; nf++)
#pragma unroll
            for (int k = 0; k < 4; k++) S[nf][k] = 0.f;

#pragma unroll
        for (int ks = 0; ks < 8; ks++) {
#pragma unroll
            for (int nf = 0; nf < 8; nf++) {
                unsigned bb[2];
                bb[0] = Ks[(nf * 8 + g) * PSTR + ks * 8 + tg    ];
                bb[1] = Ks[(nf * 8 + g) * PSTR + ks * 8 + tg + 4];
                mma_tf32(S[nf], qf[ks], bb);
            }
        }

        // ---- scale + causal mask ----
        const bool diag = (kt == qt);
#pragma unroll
        for (int nf = 0; nf < 8; nf++) {
            int kc0 = kbase + nf * 8 + 2 * tg;
            S[nf][0] *= 0.125f; S[nf][1] *= 0.125f;
            S[nf][2] *= 0.125f; S[nf][3] *= 0.125f;
            if (diag) {
                if (kc0     > q0) S[nf][0] = -1e30f;
                if (kc0 + 1 > q0) S[nf][1] = -1e30f;
                if (kc0     > q1) S[nf][2] = -1e30f;
                if (kc0 + 1 > q1) S[nf][3] = -1e30f;
            }
        }

        // ---- online softmax ----
        float mx0 = -1e30f, mx1 = -1e30f;
#pragma unroll
        for (int nf = 0; nf < 8; nf++) {
            mx0 = fmaxf(mx0, fmaxf(S[nf][0], S[nf][1]));
            mx1 = fmaxf(mx1, fmaxf(S[nf][2], S[nf][3]));
        }
        mx0 = fmaxf(mx0, __shfl_xor_sync(0xffffffffu, mx0, 1));
        mx0 = fmaxf(mx0, __shfl_xor_sync(0xffffffffu, mx0, 2));
        mx1 = fmaxf(mx1, __shfl_xor_sync(0xffffffffu, mx1, 1));
        mx1 = fmaxf(mx1, __shfl_xor_sync(0xffffffffu, mx1, 2));

        float mn0 = fmaxf(m0, mx0), mn1 = fmaxf(m1, mx1);
        float fac0 = __expf(m0 - mn0), fac1 = __expf(m1 - mn1);

        float s0 = 0.f, s1 = 0.f;
#pragma unroll
        for (int nf = 0; nf < 8; nf++) {
            S[nf][0] = __expf(S[nf][0] - mn0);
            S[nf][1] = __expf(S[nf][1] - mn0);
            S[nf][2] = __expf(S[nf][2] - mn1);
            S[nf][3] = __expf(S[nf][3] - mn1);
            s0 += S[nf][0] + S[nf][1];
            s1 += S[nf][2] + S[nf][3];
        }
        s0 += __shfl_xor_sync(0xffffffffu, s0, 1);
        s0 += __shfl_xor_sync(0xffffffffu, s0, 2);
        s1 += __shfl_xor_sync(0xffffffffu, s1, 1);
        s1 += __shfl_xor_sync(0xffffffffu, s1, 2);

        l0 = l0 * fac0 + s0; l1 = l1 * fac1 + s1;
        m0 = mn0; m1 = mn1;
#pragma unroll
        for (int nf = 0; nf < 8; nf++) {
            O[nf][0] *= fac0; O[nf][1] *= fac0;
            O[nf][2] *= fac1; O[nf][3] *= fac1;
        }

        // ---- P -> smem (per-warp rows), then O += P V ----
        {
            int row = warp * 16;
#pragma unroll
            for (int nf = 0; nf < 8; nf++) {
                int col = nf * 8 + 2 * tg;
                Ps[(row + g    ) * PSTR + col    ] = f2tf(S[nf][0]);
                Ps[(row + g    ) * PSTR + col + 1] = f2tf(S[nf][1]);
                Ps[(row + g + 8) * PSTR + col    ] = f2tf(S[nf][2]);
                Ps[(row + g + 8) * PSTR + col + 1] = f2tf(S[nf][3]);
            }
        }
        __syncwarp();

#pragma unroll
        for (int ks = 0; ks < 8; ks++) {
            unsigned a[4];
            int row = warp * 16;
            a[0] = Ps[(row + g    ) * PSTR + ks * 8 + tg    ];
            a[1] = Ps[(row + g + 8) * PSTR + ks * 8 + tg    ];
            a[2] = Ps[(row + g    ) * PSTR + ks * 8 + tg + 4];
            a[3] = Ps[(row + g + 8) * PSTR + ks * 8 + tg + 4];
#pragma unroll
            for (int nf = 0; nf < 8; nf++) {
                unsigned bb[2];
                bb[0] = Vs[(ks * 8 + tg    ) * VSTR + nf * 8 + g];
                bb[1] = Vs[(ks * 8 + tg + 4) * VSTR + nf * 8 + g];
                mma_tf32(O[nf], a, bb);
            }
        }
        __syncwarp();
    }

    // ---- normalize + write ----
    float inv0 = 1.0f / l0, inv1 = 1.0f / l1;
    float* Ag = g_A + base;
#pragma unroll
    for (int nf = 0; nf < 8; nf++) {
        int col = nf * 8 + 2 * tg;
        *(float2*)(Ag + (size_t)q0 * D_MODEL + col) =
            make_float2(O[nf][0] * inv0, O[nf][1] * inv0);
        *(float2*)(Ag + (size_t)q1 * D_MODEL + col) =
            make_float2(O[nf][2] * inv1, O[nf][3] * inv1);
    }
}

// ---------------- launch -----------------------------------------------------
extern "C" void kernel_launch(void* const* d_in, const int* in_sizes, int n_in,
                              void* d_out, int out_size)
{
    (void)in_sizes; (void)n_in; (void)out_size;
    const float* in_Q = (const float*)d_in[0];
    const float* in_K = (const float*)d_in[1];
    const float* in_V = (const float*)d_in[2];
    const float* Wq   = (const float*)d_in[3];
    const float* bq   = (const float*)d_in[4];
    const float* Wk   = (const float*)d_in[5];
    const float* bk   = (const float*)d_in[6];
    const float* Wv   = (const float*)d_in[7];
    const float* bv   = (const float*)d_in[8];
    const float* Wo   = (const float*)d_in[9];
    const float* bo   = (const float*)d_in[10];
    float* out = (float*)d_out;

    float *qp, *kp, *vp, *ap;
    cudaGetSymbolAddress((void**)&qp, g_Q);
    cudaGetSymbolAddress((void**)&kp, g_K);
    cudaGetSymbolAddress((void**)&vp, g_V);
    cudaGetSymbolAddress((void**)&ap, g_A);

    cudaFuncSetAttribute(gemm_qkv_kernel,
                         cudaFuncAttributeMaxDynamicSharedMemorySize, GEMM_SMEM);
    cudaFuncSetAttribute(gemm_one_kernel,
                         cudaFuncAttributeMaxDynamicSharedMemorySize, GEMM_SMEM);
    cudaFuncSetAttribute(flash_tf32_kernel,
                         cudaFuncAttributeMaxDynamicSharedMemorySize, FLASH_SMEM);

    dim3 qkv_grid(D_MODEL / 128, M_TOT / 128, 3);   // (8, 32, 3)
    gemm_qkv_kernel<<<qkv_grid, 256, GEMM_SMEM>>>(
        in_Q, in_K, in_V, Wq, Wk, Wv, bq, bk, bv, qp, kp, vp);

    dim3 fgrid(SEQ / 64, BATCH * N_HEADS);          // (32, 32)
    flash_tf32_kernel<<<fgrid, 128, FLASH_SMEM>>>();

    dim3 o_grid(D_MODEL / 128, M_TOT / 128);        // (8, 32)
    gemm_one_kernel<<<o_grid, 256, GEMM_SMEM>>>(ap, Wo, bo, out);
}

// round 9
// speedup vs baseline: 1.2157x; 1.1832x over previous
#include <cuda_runtime.h>
#include <math.h>
#include <stdint.h>

// Problem constants
#define D_MODEL 1024
#define N_HEADS 16
#define DKH     64
#define BATCH   2
#define SEQ     2048
#define M_TOT   (BATCH * SEQ)   // 4096

// ---------------- scratch ----------------------------------------------------
__device__ float g_Q[M_TOT * D_MODEL];
__device__ float g_K[M_TOT * D_MODEL];
__device__ float g_V[M_TOT * D_MODEL];
__device__ float g_A[M_TOT * D_MODEL];
// pre-rounded (tf32) copies of inputs and weights
__device__ float g_Xq[M_TOT * D_MODEL];
__device__ float g_Xk[M_TOT * D_MODEL];
__device__ float g_Xv[M_TOT * D_MODEL];
__device__ float g_Wq[D_MODEL * D_MODEL];
__device__ float g_Wk[D_MODEL * D_MODEL];
__device__ float g_Wv[D_MODEL * D_MODEL];
__device__ float g_Wo[D_MODEL * D_MODEL];

// ---------------- helpers ----------------------------------------------------
__device__ __forceinline__ unsigned f2tf(float f) {
    unsigned r;
    asm("cvt.rna.tf32.f32 %0, %1;" : "=r"(r) : "f"(f));
    return r;
}

__device__ __forceinline__ uint32_t s2u(const void* p) {
    uint32_t a;
    asm("{ .reg .u64 t; cvta.to.shared.u64 t, %1; cvt.u32.u64 %0, t; }"
        : "=r"(a) : "l"(p));
    return a;
}

__device__ __forceinline__ void cpa16(uint32_t s, const void* g) {
    asm volatile("cp.async.cg.shared.global [%0], [%1], 16;" :: "r"(s), "l"(g));
}

__device__ __forceinline__ void mma_tf32(float* c, const unsigned* a, const unsigned* b) {
    asm volatile(
        "mma.sync.aligned.m16n8k8.row.col.f32.tf32.tf32.f32 "
        "{%0,%1,%2,%3}, {%4,%5,%6,%7}, {%8,%9}, {%0,%1,%2,%3};"
        : "+f"(c[0]), "+f"(c[1]), "+f"(c[2]), "+f"(c[3])
        : "r"(a[0]), "r"(a[1]), "r"(a[2]), "r"(a[3]), "r"(b[0]), "r"(b[1]));
}

// ---------------- pre-round pass: fp32 -> tf32-rounded fp32 ------------------
// z 0..2: inputs (1M float4 each), z 3..6: weights (256K float4 each)
__global__ __launch_bounds__(256) void preround_kernel(
    const float* __restrict__ i0, const float* __restrict__ i1, const float* __restrict__ i2,
    const float* __restrict__ w0, const float* __restrict__ w1,
    const float* __restrict__ w2, const float* __restrict__ w3,
    float* __restrict__ o0, float* __restrict__ o1, float* __restrict__ o2,
    float* __restrict__ o3, float* __restrict__ o4, float* __restrict__ o5,
    float* __restrict__ o6)
{
    const int z = blockIdx.z;
    const float* src;
    float* dst;
    int n4;
    switch (z) {
        case 0: src = i0; dst = o0; n4 = M_TOT * D_MODEL / 4; break;
        case 1: src = i1; dst = o1; n4 = M_TOT * D_MODEL / 4; break;
        case 2: src = i2; dst = o2; n4 = M_TOT * D_MODEL / 4; break;
        case 3: src = w0; dst = o3; n4 = D_MODEL * D_MODEL / 4; break;
        case 4: src = w1; dst = o4; n4 = D_MODEL * D_MODEL / 4; break;
        case 5: src = w2; dst = o5; n4 = D_MODEL * D_MODEL / 4; break;
        default: src = w3; dst = o6; n4 = D_MODEL * D_MODEL / 4; break;
    }
    const int idx    = blockIdx.x * 256 + threadIdx.x;
    const int stride = gridDim.x * 256;
    for (int i = idx; i < n4; i += stride) {
        float4 v = ((const float4*)src)[i];
        uint4 r  = make_uint4(f2tf(v.x), f2tf(v.y), f2tf(v.z), f2tf(v.w));
        ((uint4*)dst)[i] = r;
    }
}

// ---------------- GEMM: Y = X[M,K] * W[N,K]^T + bias -------------------------
// 256 thr / 8 warps, CTA tile 128x128, BK=32, warp tile 64x32.
// Inputs pre-rounded to tf32 -> cp.async double-buffered staging, NO cvt.
#define GSTR      36                        // 36 % 32 == 4 -> conflict-free frags
#define GEMM_NCH  (D_MODEL / 32)            // 32 chunks
#define GEMM_BUF  (128 * GSTR)              // words per operand buffer
#define GEMM_SMEM (4 * GEMM_BUF * 4)        // 73728 B

template <bool ROUND_OUT>
__device__ __forceinline__ void gemm_body(
    const float* __restrict__ X, const float* __restrict__ W,
    const float* __restrict__ bias, float* __restrict__ Y,
    unsigned* smem)
{
    const int N = D_MODEL, K = D_MODEL;

    unsigned* Xb[2] = { smem,                smem + GEMM_BUF };
    unsigned* Wb[2] = { smem + 2 * GEMM_BUF, smem + 3 * GEMM_BUF };

    const int tid  = threadIdx.x;
    const int warp = tid >> 5, lane = tid & 31;
    const int wm = warp >> 2, wn = warp & 3;
    const int g  = lane >> 2, tg = lane & 3;
    const int bm = blockIdx.y * 128, bn = blockIdx.x * 128;

    const int lr = tid >> 3;         // 0..31
    const int lc = (tid & 7) * 4;    // 0..28

    const float* xg = X + (size_t)(bm + lr) * K + lc;
    const float* wg = W + (size_t)(bn + lr) * K + lc;
    const uint32_t sx[2] = { s2u(Xb[0] + lr * GSTR + lc), s2u(Xb[1] + lr * GSTR + lc) };
    const uint32_t sw[2] = { s2u(Wb[0] + lr * GSTR + lc), s2u(Wb[1] + lr * GSTR + lc) };

    float c[4][4][4];
#pragma unroll
    for (int mf = 0; mf < 4; mf++)
#pragma unroll
        for (int nf = 0; nf < 4; nf++)
#pragma unroll
            for (int k = 0; k < 4; k++) c[mf][nf][k] = 0.f;

    auto issue = [&](int ch, int buf) {
        const float* xp = xg + ch * 32;
        const float* wp = wg + ch * 32;
#pragma unroll
        for (int i = 0; i < 4; i++) {
            cpa16(sx[buf] + (uint32_t)(i * 32 * GSTR * 4), xp + (size_t)(i * 32) * K);
            cpa16(sw[buf] + (uint32_t)(i * 32 * GSTR * 4), wp + (size_t)(i * 32) * K);
        }
        asm volatile("cp.async.commit_group;" ::: "memory");
    };

    issue(0, 0);

    for (int ch = 0; ch < GEMM_NCH; ch++) {
        const int buf = ch & 1;
        if (ch + 1 < GEMM_NCH) {
            issue(ch + 1, buf ^ 1);
            asm volatile("cp.async.wait_group 1;" ::: "memory");
        } else {
            asm volatile("cp.async.wait_group 0;" ::: "memory");
        }
        __syncthreads();

        const unsigned* Xs = Xb[buf];
        const unsigned* Ws = Wb[buf];
#pragma unroll
        for (int ks = 0; ks < 4; ks++) {
            unsigned a[4][4], b[4][2];
#pragma unroll
            for (int mf = 0; mf < 4; mf++) {
                int row = wm * 64 + mf * 16;
                a[mf][0] = Xs[(row + g    ) * GSTR + ks * 8 + tg    ];
                a[mf][1] = Xs[(row + g + 8) * GSTR + ks * 8 + tg    ];
                a[mf][2] = Xs[(row + g    ) * GSTR + ks * 8 + tg + 4];
                a[mf][3] = Xs[(row + g + 8) * GSTR + ks * 8 + tg + 4];
            }
#pragma unroll
            for (int nf = 0; nf < 4; nf++) {
                int col = wn * 32 + nf * 8 + g;
                b[nf][0] = Ws[col * GSTR + ks * 8 + tg    ];
                b[nf][1] = Ws[col * GSTR + ks * 8 + tg + 4];
            }
#pragma unroll
            for (int mf = 0; mf < 4; mf++)
#pragma unroll
                for (int nf = 0; nf < 4; nf++)
                    mma_tf32(c[mf][nf], a[mf], b[nf]);
        }
        __syncthreads();
    }

    // epilogue: bias + (optional tf32 rounding) + store
#pragma unroll
    for (int mf = 0; mf < 4; mf++) {
#pragma unroll
        for (int nf = 0; nf < 4; nf++) {
            int row = bm + wm * 64 + mf * 16 + g;
            int col = bn + wn * 32 + nf * 8 + 2 * tg;
            float b0 = bias[col], b1 = bias[col + 1];
            float v0 = c[mf][nf][0] + b0, v1 = c[mf][nf][1] + b1;
            float v2 = c[mf][nf][2] + b0, v3 = c[mf][nf][3] + b1;
            if (ROUND_OUT) {
                v0 = __uint_as_float(f2tf(v0)); v1 = __uint_as_float(f2tf(v1));
                v2 = __uint_as_float(f2tf(v2)); v3 = __uint_as_float(f2tf(v3));
            }
            *(float2*)(Y + (size_t)row * N + col)       = make_float2(v0, v1);
            *(float2*)(Y + (size_t)(row + 8) * N + col) = make_float2(v2, v3);
        }
    }
}

// Fused QKV projection: blockIdx.z selects operands; outputs tf32-rounded.
__global__ __launch_bounds__(256, 2)
void gemm_qkv_kernel(const float* __restrict__ X0, const float* __restrict__ X1,
                     const float* __restrict__ X2,
                     const float* __restrict__ W0, const float* __restrict__ W1,
                     const float* __restrict__ W2,
                     const float* __restrict__ b0, const float* __restrict__ b1,
                     const float* __restrict__ b2,
                     float* __restrict__ Y0, float* __restrict__ Y1,
                     float* __restrict__ Y2)
{
    extern __shared__ unsigned gsm[];
    const int z = blockIdx.z;
    const float* X = (z == 0) ? X0 : (z == 1) ? X1 : X2;
    const float* W = (z == 0) ? W0 : (z == 1) ? W1 : W2;
    const float* B = (z == 0) ? b0 : (z == 1) ? b1 : b2;
    float*       Y = (z == 0) ? Y0 : (z == 1) ? Y1 : Y2;
    gemm_body<true>(X, W, B, Y, gsm);
}

// O-projection: fp32 output (final result).
__global__ __launch_bounds__(256, 2)
void gemm_one_kernel(const float* __restrict__ X, const float* __restrict__ W,
                     const float* __restrict__ bias, float* __restrict__ Y)
{
    extern __shared__ unsigned gsm[];
    gemm_body<false>(X, W, bias, Y, gsm);
}

// ---------------- flash attention, tf32 mma (BQ=64) --------------------------
// 128 thr / 4 warps, 64 q-rows per block, KV tiles of 64.
// g_Q/g_K/g_V are tf32-rounded -> cp.async staging, NO cvt.
#define PSTR 68   // g-indexed rows: 68 % 32 == 4
#define VSTR 72   // tg-indexed rows: 72 % 32 == 8
#define FLASH_SMEM ((64 * PSTR * 2 + 64 * VSTR) * 4)

__global__ __launch_bounds__(128, 4)
void flash_tf32_kernel()
{
    extern __shared__ unsigned sm[];
    unsigned* Ps = sm;                   // [64][PSTR]  (Q staging, then P)
    unsigned* Ks = Ps + 64 * PSTR;       // [64][PSTR]
    unsigned* Vs = Ks + 64 * PSTR;       // [64][VSTR]

    const int tid  = threadIdx.x;
    const int warp = tid >> 5, lane = tid & 31;
    const int g = lane >> 2, tg = lane & 3;
    const int qt = (int)gridDim.x - 1 - (int)blockIdx.x;   // heavy blocks first
    const int bh = blockIdx.y;
    const int b  = bh >> 4, h = bh & 15;
    const int qbase = qt * 64;

    const size_t base = (size_t)b * SEQ * D_MODEL + (size_t)h * DKH;
    const float* Qg = g_Q + base;
    const float* Kg = g_K + base;
    const float* Vg = g_V + base;

    const int sr = tid >> 4;         // staging row 0..7
    const int sc = (tid & 15) * 4;   // staging col 0..60

    const uint32_t psU = s2u(&Ps[sr * PSTR + sc]);
    const uint32_t ksU = s2u(&Ks[sr * PSTR + sc]);
    const uint32_t vsU = s2u(&Vs[sr * VSTR + sc]);

    // ---- stage Q via cp.async ----
#pragma unroll
    for (int p = 0; p < 8; p++) {
        int r = sr + 8 * p;
        cpa16(psU + (uint32_t)(8 * p * PSTR * 4), Qg + (size_t)(qbase + r) * D_MODEL + sc);
    }
    asm volatile("cp.async.commit_group;" ::: "memory");
    asm volatile("cp.async.wait_group 0;" ::: "memory");
    __syncthreads();

    unsigned qf[8][4];
    {
        int row = warp * 16;
#pragma unroll
        for (int ks = 0; ks < 8; ks++) {
            qf[ks][0] = Ps[(row + g    ) * PSTR + ks * 8 + tg    ];
            qf[ks][1] = Ps[(row + g + 8) * PSTR + ks * 8 + tg    ];
            qf[ks][2] = Ps[(row + g    ) * PSTR + ks * 8 + tg + 4];
            qf[ks][3] = Ps[(row + g + 8) * PSTR + ks * 8 + tg + 4];
        }
    }

    float O[8][4];
#pragma unroll
    for (int nf = 0; nf < 8; nf++)
#pragma unroll
        for (int k = 0; k < 4; k++) O[nf][k] = 0.f;
    float m0 = -1e30f, m1 = -1e30f, l0 = 0.f, l1 = 0.f;

    const int q0 = qbase + warp * 16 + g;
    const int q1 = q0 + 8;

    const int nkt = qt + 1;
    for (int kt = 0; kt < nkt; kt++) {
        const int kbase = kt * 64;
        __syncthreads();
        // ---- stage K,V via cp.async ----
#pragma unroll
        for (int p = 0; p < 8; p++) {
            int r = sr + 8 * p;
            cpa16(ksU + (uint32_t)(8 * p * PSTR * 4), Kg + (size_t)(kbase + r) * D_MODEL + sc);
            cpa16(vsU + (uint32_t)(8 * p * VSTR * 4), Vg + (size_t)(kbase + r) * D_MODEL + sc);
        }
        asm volatile("cp.async.commit_group;" ::: "memory");
        asm volatile("cp.async.wait_group 0;" ::: "memory");
        __syncthreads();

        // ---- S = Q K^T ----
        float S[8][4];
#pragma unroll
        for (int nf = 0; nf < 8; nf++)
#pragma unroll
            for (int k = 0; k < 4; k++) S[nf][k] = 0.f;

#pragma unroll
        for (int ks = 0; ks < 8; ks++) {
#pragma unroll
            for (int nf = 0; nf < 8; nf++) {
                unsigned bb[2];
                bb[0] = Ks[(nf * 8 + g) * PSTR + ks * 8 + tg    ];
                bb[1] = Ks[(nf * 8 + g) * PSTR + ks * 8 + tg + 4];
                mma_tf32(S[nf], qf[ks], bb);
            }
        }

        // ---- scale + causal mask ----
        const bool diag = (kt == qt);
#pragma unroll
        for (int nf = 0; nf < 8; nf++) {
            int kc0 = kbase + nf * 8 + 2 * tg;
            S[nf][0] *= 0.125f; S[nf][1] *= 0.125f;
            S[nf][2] *= 0.125f; S[nf][3] *= 0.125f;
            if (diag) {
                if (kc0     > q0) S[nf][0] = -1e30f;
                if (kc0 + 1 > q0) S[nf][1] = -1e30f;
                if (kc0     > q1) S[nf][2] = -1e30f;
                if (kc0 + 1 > q1) S[nf][3] = -1e30f;
            }
        }

        // ---- online softmax ----
        float mx0 = -1e30f, mx1 = -1e30f;
#pragma unroll
        for (int nf = 0; nf < 8; nf++) {
            mx0 = fmaxf(mx0, fmaxf(S[nf][0], S[nf][1]));
            mx1 = fmaxf(mx1, fmaxf(S[nf][2], S[nf][3]));
        }
        mx0 = fmaxf(mx0, __shfl_xor_sync(0xffffffffu, mx0, 1));
        mx0 = fmaxf(mx0, __shfl_xor_sync(0xffffffffu, mx0, 2));
        mx1 = fmaxf(mx1, __shfl_xor_sync(0xffffffffu, mx1, 1));
        mx1 = fmaxf(mx1, __shfl_xor_sync(0xffffffffu, mx1, 2));

        float mn0 = fmaxf(m0, mx0), mn1 = fmaxf(m1, mx1);
        float fac0 = __expf(m0 - mn0), fac1 = __expf(m1 - mn1);

        float s0 = 0.f, s1 = 0.f;
#pragma unroll
        for (int nf = 0; nf < 8; nf++) {
            S[nf][0] = __expf(S[nf][0] - mn0);
            S[nf][1] = __expf(S[nf][1] - mn0);
            S[nf][2] = __expf(S[nf][2] - mn1);
            S[nf][3] = __expf(S[nf][3] - mn1);
            s0 += S[nf][0] + S[nf][1];
            s1 += S[nf][2] + S[nf][3];
        }
        s0 += __shfl_xor_sync(0xffffffffu, s0, 1);
        s0 += __shfl_xor_sync(0xffffffffu, s0, 2);
        s1 += __shfl_xor_sync(0xffffffffu, s1, 1);
        s1 += __shfl_xor_sync(0xffffffffu, s1, 2);

        l0 = l0 * fac0 + s0; l1 = l1 * fac1 + s1;
        m0 = mn0; m1 = mn1;
#pragma unroll
        for (int nf = 0; nf < 8; nf++) {
            O[nf][0] *= fac0; O[nf][1] *= fac0;
            O[nf][2] *= fac1; O[nf][3] *= fac1;
        }

        // ---- P -> smem (per-warp rows), then O += P V ----
        {
            int row = warp * 16;
#pragma unroll
            for (int nf = 0; nf < 8; nf++) {
                int col = nf * 8 + 2 * tg;
                Ps[(row + g    ) * PSTR + col    ] = f2tf(S[nf][0]);
                Ps[(row + g    ) * PSTR + col + 1] = f2tf(S[nf][1]);
                Ps[(row + g + 8) * PSTR + col    ] = f2tf(S[nf][2]);
                Ps[(row + g + 8) * PSTR + col + 1] = f2tf(S[nf][3]);
            }
        }
        __syncwarp();

#pragma unroll
        for (int ks = 0; ks < 8; ks++) {
            unsigned a[4];
            int row = warp * 16;
            a[0] = Ps[(row + g    ) * PSTR + ks * 8 + tg    ];
            a[1] = Ps[(row + g + 8) * PSTR + ks * 8 + tg    ];
            a[2] = Ps[(row + g    ) * PSTR + ks * 8 + tg + 4];
            a[3] = Ps[(row + g + 8) * PSTR + ks * 8 + tg + 4];
#pragma unroll
            for (int nf = 0; nf < 8; nf++) {
                unsigned bb[2];
                bb[0] = Vs[(ks * 8 + tg    ) * VSTR + nf * 8 + g];
                bb[1] = Vs[(ks * 8 + tg + 4) * VSTR + nf * 8 + g];
                mma_tf32(O[nf], a, bb);
            }
        }
        __syncwarp();
    }

    // ---- normalize + write (tf32-rounded so O-proj can cp.async) ----
    float inv0 = 1.0f / l0, inv1 = 1.0f / l1;
    float* Ag = g_A + base;
#pragma unroll
    for (int nf = 0; nf < 8; nf++) {
        int col = nf * 8 + 2 * tg;
        float2 o0 = make_float2(__uint_as_float(f2tf(O[nf][0] * inv0)),
                                __uint_as_float(f2tf(O[nf][1] * inv0)));
        float2 o1 = make_float2(__uint_as_float(f2tf(O[nf][2] * inv1)),
                                __uint_as_float(f2tf(O[nf][3] * inv1)));
        *(float2*)(Ag + (size_t)q0 * D_MODEL + col) = o0;
        *(float2*)(Ag + (size_t)q1 * D_MODEL + col) = o1;
    }
}

// ---------------- launch -----------------------------------------------------
extern "C" void kernel_launch(void* const* d_in, const int* in_sizes, int n_in,
                              void* d_out, int out_size)
{
    (void)in_sizes; (void)n_in; (void)out_size;
    const float* in_Q = (const float*)d_in[0];
    const float* in_K = (const float*)d_in[1];
    const float* in_V = (const float*)d_in[2];
    const float* Wq   = (const float*)d_in[3];
    const float* bq   = (const float*)d_in[4];
    const float* Wk   = (const float*)d_in[5];
    const float* bk   = (const float*)d_in[6];
    const float* Wv   = (const float*)d_in[7];
    const float* bv   = (const float*)d_in[8];
    const float* Wo   = (const float*)d_in[9];
    const float* bo   = (const float*)d_in[10];
    float* out = (float*)d_out;

    float *qp, *kp, *vp, *ap;
    float *xq, *xk, *xv, *wq, *wk, *wv, *wo;
    cudaGetSymbolAddress((void**)&qp, g_Q);
    cudaGetSymbolAddress((void**)&kp, g_K);
    cudaGetSymbolAddress((void**)&vp, g_V);
    cudaGetSymbolAddress((void**)&ap, g_A);
    cudaGetSymbolAddress((void**)&xq, g_Xq);
    cudaGetSymbolAddress((void**)&xk, g_Xk);
    cudaGetSymbolAddress((void**)&xv, g_Xv);
    cudaGetSymbolAddress((void**)&wq, g_Wq);
    cudaGetSymbolAddress((void**)&wk, g_Wk);
    cudaGetSymbolAddress((void**)&wv, g_Wv);
    cudaGetSymbolAddress((void**)&wo, g_Wo);

    cudaFuncSetAttribute(gemm_qkv_kernel,
                         cudaFuncAttributeMaxDynamicSharedMemorySize, GEMM_SMEM);
    cudaFuncSetAttribute(gemm_one_kernel,
                         cudaFuncAttributeMaxDynamicSharedMemorySize, GEMM_SMEM);
    cudaFuncSetAttribute(flash_tf32_kernel,
                         cudaFuncAttributeMaxDynamicSharedMemorySize, FLASH_SMEM);

    // 1) pre-round inputs + weights to tf32
    dim3 pr_grid(1024, 1, 7);
    preround_kernel<<<pr_grid, 256>>>(in_Q, in_K, in_V, Wq, Wk, Wv, Wo,
                                      xq, xk, xv, wq, wk, wv, wo);

    // 2) fused QKV projections (outputs tf32-rounded)
    dim3 qkv_grid(D_MODEL / 128, M_TOT / 128, 3);   // (8, 32, 3)
    gemm_qkv_kernel<<<qkv_grid, 256, GEMM_SMEM>>>(
        xq, xk, xv, wq, wk, wv, bq, bk, bv, qp, kp, vp);

    // 3) flash attention (writes tf32-rounded g_A)
    dim3 fgrid(SEQ / 64, BATCH * N_HEADS);          // (32, 32)
    flash_tf32_kernel<<<fgrid, 128, FLASH_SMEM>>>();

    // 4) output projection (fp32 result)
    dim3 o_grid(D_MODEL / 128, M_TOT / 128);        // (8, 32)
    gemm_one_kernel<<<o_grid, 256, GEMM_SMEM>>>(ap, wo, bo, out);
}

// round 10
// speedup vs baseline: 1.2396x; 1.0197x over previous
#include <cuda_runtime.h>
#include <math.h>
#include <stdint.h>

// Problem constants
#define D_MODEL 1024
#define N_HEADS 16
#define DKH     64
#define BATCH   2
#define SEQ     2048
#define M_TOT   (BATCH * SEQ)   // 4096

// ---------------- scratch ----------------------------------------------------
__device__ float g_Q[M_TOT * D_MODEL];
__device__ float g_K[M_TOT * D_MODEL];
__device__ float g_V[M_TOT * D_MODEL];
__device__ float g_A[M_TOT * D_MODEL];
// pre-rounded (tf32) copies of inputs and weights
__device__ float g_Xq[M_TOT * D_MODEL];
__device__ float g_Xk[M_TOT * D_MODEL];
__device__ float g_Xv[M_TOT * D_MODEL];
__device__ float g_Wq[D_MODEL * D_MODEL];
__device__ float g_Wk[D_MODEL * D_MODEL];
__device__ float g_Wv[D_MODEL * D_MODEL];
__device__ float g_Wo[D_MODEL * D_MODEL];

// ---------------- helpers ----------------------------------------------------
__device__ __forceinline__ unsigned f2tf(float f) {
    unsigned r;
    asm("cvt.rna.tf32.f32 %0, %1;" : "=r"(r) : "f"(f));
    return r;
}

__device__ __forceinline__ uint32_t s2u(const void* p) {
    uint32_t a;
    asm("{ .reg .u64 t; cvta.to.shared.u64 t, %1; cvt.u32.u64 %0, t; }"
        : "=r"(a) : "l"(p));
    return a;
}

__device__ __forceinline__ void cpa16(uint32_t s, const void* g) {
    asm volatile("cp.async.cg.shared.global [%0], [%1], 16;" :: "r"(s), "l"(g));
}

__device__ __forceinline__ void mma_tf32(float* c, const unsigned* a, const unsigned* b) {
    asm volatile(
        "mma.sync.aligned.m16n8k8.row.col.f32.tf32.tf32.f32 "
        "{%0,%1,%2,%3}, {%4,%5,%6,%7}, {%8,%9}, {%0,%1,%2,%3};"
        : "+f"(c[0]), "+f"(c[1]), "+f"(c[2]), "+f"(c[3])
        : "r"(a[0]), "r"(a[1]), "r"(a[2]), "r"(a[3]), "r"(b[0]), "r"(b[1]));
}

// ---------------- pre-round pass: fp32 -> tf32-rounded fp32 ------------------
__global__ __launch_bounds__(256) void preround_kernel(
    const float* __restrict__ i0, const float* __restrict__ i1, const float* __restrict__ i2,
    const float* __restrict__ w0, const float* __restrict__ w1,
    const float* __restrict__ w2, const float* __restrict__ w3,
    float* __restrict__ o0, float* __restrict__ o1, float* __restrict__ o2,
    float* __restrict__ o3, float* __restrict__ o4, float* __restrict__ o5,
    float* __restrict__ o6)
{
    const int z = blockIdx.z;
    const float* src;
    float* dst;
    int n4;
    switch (z) {
        case 0: src = i0; dst = o0; n4 = M_TOT * D_MODEL / 4; break;
        case 1: src = i1; dst = o1; n4 = M_TOT * D_MODEL / 4; break;
        case 2: src = i2; dst = o2; n4 = M_TOT * D_MODEL / 4; break;
        case 3: src = w0; dst = o3; n4 = D_MODEL * D_MODEL / 4; break;
        case 4: src = w1; dst = o4; n4 = D_MODEL * D_MODEL / 4; break;
        case 5: src = w2; dst = o5; n4 = D_MODEL * D_MODEL / 4; break;
        default: src = w3; dst = o6; n4 = D_MODEL * D_MODEL / 4; break;
    }
    const int idx    = blockIdx.x * 256 + threadIdx.x;
    const int stride = gridDim.x * 256;
    for (int i = idx; i < n4; i += stride) {
        float4 v = ((const float4*)src)[i];
        uint4 r  = make_uint4(f2tf(v.x), f2tf(v.y), f2tf(v.z), f2tf(v.w));
        ((uint4*)dst)[i] = r;
    }
}

// ---------------- GEMM: Y = X[M,K] * W[N,K]^T + bias -------------------------
// 256 thr / 8 warps, CTA tile 128x128, BK=32, warp tile 64x32.
// Pre-rounded inputs -> cp.async 3-stage pipeline, ONE barrier per chunk.
#define GSTR      36                        // 36 % 32 == 4 -> conflict-free frags
#define GSTAGES   3
#define GEMM_NCH  (D_MODEL / 32)            // 32 chunks
#define GEMM_BUF  (128 * GSTR)              // words per operand per stage
#define GEMM_SMEM (2 * GSTAGES * GEMM_BUF * 4)   // 110592 B

template <bool ROUND_OUT>
__device__ __forceinline__ void gemm_body(
    const float* __restrict__ X, const float* __restrict__ W,
    const float* __restrict__ bias, float* __restrict__ Y,
    unsigned* smem)
{
    const int N = D_MODEL, K = D_MODEL;

    unsigned* Xb[GSTAGES];
    unsigned* Wb[GSTAGES];
#pragma unroll
    for (int s = 0; s < GSTAGES; s++) {
        Xb[s] = smem + s * GEMM_BUF;
        Wb[s] = smem + (GSTAGES + s) * GEMM_BUF;
    }

    const int tid  = threadIdx.x;
    const int warp = tid >> 5, lane = tid & 31;
    const int wm = warp >> 2, wn = warp & 3;
    const int g  = lane >> 2, tg = lane & 3;
    const int bm = blockIdx.y * 128, bn = blockIdx.x * 128;

    const int lr = tid >> 3;         // 0..31
    const int lc = (tid & 7) * 4;    // 0..28

    const float* xg = X + (size_t)(bm + lr) * K + lc;
    const float* wg = W + (size_t)(bn + lr) * K + lc;
    uint32_t sx[GSTAGES], sw[GSTAGES];
#pragma unroll
    for (int s = 0; s < GSTAGES; s++) {
        sx[s] = s2u(Xb[s] + lr * GSTR + lc);
        sw[s] = s2u(Wb[s] + lr * GSTR + lc);
    }

    float c[4][4][4];
#pragma unroll
    for (int mf = 0; mf < 4; mf++)
#pragma unroll
        for (int nf = 0; nf < 4; nf++)
#pragma unroll
            for (int k = 0; k < 4; k++) c[mf][nf][k] = 0.f;

    // issue staging for chunk ch (if valid) into stage buf; ALWAYS commit
    auto issue = [&](int ch, int buf) {
        if (ch < GEMM_NCH) {
            const float* xp = xg + ch * 32;
            const float* wp = wg + ch * 32;
#pragma unroll
            for (int i = 0; i < 4; i++) {
                cpa16(sx[buf] + (uint32_t)(i * 32 * GSTR * 4), xp + (size_t)(i * 32) * K);
                cpa16(sw[buf] + (uint32_t)(i * 32 * GSTR * 4), wp + (size_t)(i * 32) * K);
            }
        }
        asm volatile("cp.async.commit_group;" ::: "memory");
    };

    issue(0, 0);
    issue(1, 1);

    for (int ch = 0; ch < GEMM_NCH; ch++) {
        const int buf = ch % GSTAGES;
        // wait until chunk ch's group is complete (<=1 groups still pending)
        asm volatile("cp.async.wait_group 1;" ::: "memory");
        __syncthreads();
        // prefetch chunk ch+2 into the stage consumed at ch-1 (all warps past it)
        issue(ch + 2, (ch + 2) % GSTAGES);

        const unsigned* Xs = Xb[buf];
        const unsigned* Ws = Wb[buf];
#pragma unroll
        for (int ks = 0; ks < 4; ks++) {
            unsigned a[4][4], b[4][2];
#pragma unroll
            for (int mf = 0; mf < 4; mf++) {
                int row = wm * 64 + mf * 16;
                a[mf][0] = Xs[(row + g    ) * GSTR + ks * 8 + tg    ];
                a[mf][1] = Xs[(row + g + 8) * GSTR + ks * 8 + tg    ];
                a[mf][2] = Xs[(row + g    ) * GSTR + ks * 8 + tg + 4];
                a[mf][3] = Xs[(row + g + 8) * GSTR + ks * 8 + tg + 4];
            }
#pragma unroll
            for (int nf = 0; nf < 4; nf++) {
                int col = wn * 32 + nf * 8 + g;
                b[nf][0] = Ws[col * GSTR + ks * 8 + tg    ];
                b[nf][1] = Ws[col * GSTR + ks * 8 + tg + 4];
            }
#pragma unroll
            for (int mf = 0; mf < 4; mf++)
#pragma unroll
                for (int nf = 0; nf < 4; nf++)
                    mma_tf32(c[mf][nf], a[mf], b[nf]);
        }
    }

    // epilogue: bias + (optional tf32 rounding) + store
#pragma unroll
    for (int mf = 0; mf < 4; mf++) {
#pragma unroll
        for (int nf = 0; nf < 4; nf++) {
            int row = bm + wm * 64 + mf * 16 + g;
            int col = bn + wn * 32 + nf * 8 + 2 * tg;
            float b0 = bias[col], b1 = bias[col + 1];
            float v0 = c[mf][nf][0] + b0, v1 = c[mf][nf][1] + b1;
            float v2 = c[mf][nf][2] + b0, v3 = c[mf][nf][3] + b1;
            if (ROUND_OUT) {
                v0 = __uint_as_float(f2tf(v0)); v1 = __uint_as_float(f2tf(v1));
                v2 = __uint_as_float(f2tf(v2)); v3 = __uint_as_float(f2tf(v3));
            }
            *(float2*)(Y + (size_t)row * N + col)       = make_float2(v0, v1);
            *(float2*)(Y + (size_t)(row + 8) * N + col) = make_float2(v2, v3);
        }
    }
}

// Fused QKV projection: blockIdx.z selects operands; outputs tf32-rounded.
__global__ __launch_bounds__(256, 2)
void gemm_qkv_kernel(const float* __restrict__ X0, const float* __restrict__ X1,
                     const float* __restrict__ X2,
                     const float* __restrict__ W0, const float* __restrict__ W1,
                     const float* __restrict__ W2,
                     const float* __restrict__ b0, const float* __restrict__ b1,
                     const float* __restrict__ b2,
                     float* __restrict__ Y0, float* __restrict__ Y1,
                     float* __restrict__ Y2)
{
    extern __shared__ unsigned gsm[];
    const int z = blockIdx.z;
    const float* X = (z == 0) ? X0 : (z == 1) ? X1 : X2;
    const float* W = (z == 0) ? W0 : (z == 1) ? W1 : W2;
    const float* B = (z == 0) ? b0 : (z == 1) ? b1 : b2;
    float*       Y = (z == 0) ? Y0 : (z == 1) ? Y1 : Y2;
    gemm_body<true>(X, W, B, Y, gsm);
}

// O-projection: fp32 output (final result).
__global__ __launch_bounds__(256, 2)
void gemm_one_kernel(const float* __restrict__ X, const float* __restrict__ W,
                     const float* __restrict__ bias, float* __restrict__ Y)
{
    extern __shared__ unsigned gsm[];
    gemm_body<false>(X, W, bias, Y, gsm);
}

// ---------------- flash attention, tf32 mma (BQ=64) --------------------------
// 128 thr / 4 warps, 64 q-rows per block, KV tiles of 64.
// g_Q/g_K/g_V are tf32-rounded -> cp.async staging, NO cvt.
#define PSTR 68   // g-indexed rows: 68 % 32 == 4
#define VSTR 72   // tg-indexed rows: 72 % 32 == 8
#define FLASH_SMEM ((64 * PSTR * 2 + 64 * VSTR) * 4)

__global__ __launch_bounds__(128, 4)
void flash_tf32_kernel()
{
    extern __shared__ unsigned sm[];
    unsigned* Ps = sm;                   // [64][PSTR]  (Q staging, then P)
    unsigned* Ks = Ps + 64 * PSTR;       // [64][PSTR]
    unsigned* Vs = Ks + 64 * PSTR;       // [64][VSTR]

    const int tid  = threadIdx.x;
    const int warp = tid >> 5, lane = tid & 31;
    const int g = lane >> 2, tg = lane & 3;
    const int qt = (int)gridDim.x - 1 - (int)blockIdx.x;   // heavy blocks first
    const int bh = blockIdx.y;
    const int b  = bh >> 4, h = bh & 15;
    const int qbase = qt * 64;

    const size_t base = (size_t)b * SEQ * D_MODEL + (size_t)h * DKH;
    const float* Qg = g_Q + base;
    const float* Kg = g_K + base;
    const float* Vg = g_V + base;

    const int sr = tid >> 4;         // staging row 0..7
    const int sc = (tid & 15) * 4;   // staging col 0..60

    const uint32_t psU = s2u(&Ps[sr * PSTR + sc]);
    const uint32_t ksU = s2u(&Ks[sr * PSTR + sc]);
    const uint32_t vsU = s2u(&Vs[sr * VSTR + sc]);

    // ---- stage Q via cp.async ----
#pragma unroll
    for (int p = 0; p < 8; p++) {
        int r = sr + 8 * p;
        cpa16(psU + (uint32_t)(8 * p * PSTR * 4), Qg + (size_t)(qbase + r) * D_MODEL + sc);
    }
    asm volatile("cp.async.commit_group;" ::: "memory");
    asm volatile("cp.async.wait_group 0;" ::: "memory");
    __syncthreads();

    unsigned qf[8][4];
    {
        int row = warp * 16;
#pragma unroll
        for (int ks = 0; ks < 8; ks++) {
            qf[ks][0] = Ps[(row + g    ) * PSTR + ks * 8 + tg    ];
            qf[ks][1] = Ps[(row + g + 8) * PSTR + ks * 8 + tg    ];
            qf[ks][2] = Ps[(row + g    ) * PSTR + ks * 8 + tg + 4];
            qf[ks][3] = Ps[(row + g + 8) * PSTR + ks * 8 + tg + 4];
        }
    }

    float O[8][4];
#pragma unroll
    for (int nf = 0; nf < 8; nf++)
#pragma unroll
        for (int k = 0; k < 4; k++) O[nf][k] = 0.f;
    float m0 = -1e30f, m1 = -1e30f, l0 = 0.f, l1 = 0.f;

    const int q0 = qbase + warp * 16 + g;
    const int q1 = q0 + 8;

    const int nkt = qt + 1;
    for (int kt = 0; kt < nkt; kt++) {
        const int kbase = kt * 64;
        __syncthreads();
        // ---- stage K,V via cp.async ----
#pragma unroll
        for (int p = 0; p < 8; p++) {
            int r = sr + 8 * p;
            cpa16(ksU + (uint32_t)(8 * p * PSTR * 4), Kg + (size_t)(kbase + r) * D_MODEL + sc);
            cpa16(vsU + (uint32_t)(8 * p * VSTR * 4), Vg + (size_t)(kbase + r) * D_MODEL + sc);
        }
        asm volatile("cp.async.commit_group;" ::: "memory");
        asm volatile("cp.async.wait_group 0;" ::: "memory");
        __syncthreads();

        // ---- S = Q K^T ----
        float S[8][4];
#pragma unroll
        for (int nf = 0; nf < 8; nf++)
#pragma unroll
            for (int k = 0; k < 4; k++) S[nf][k] = 0.f;

#pragma unroll
        for (int ks = 0; ks < 8; ks++) {
#pragma unroll
            for (int nf = 0; nf < 8; nf++) {
                unsigned bb[2];
                bb[0] = Ks[(nf * 8 + g) * PSTR + ks * 8 + tg    ];
                bb[1] = Ks[(nf * 8 + g) * PSTR + ks * 8 + tg + 4];
                mma_tf32(S[nf], qf[ks], bb);
            }
        }

        // ---- scale + causal mask ----
        const bool diag = (kt == qt);
#pragma unroll
        for (int nf = 0; nf < 8; nf++) {
            int kc0 = kbase + nf * 8 + 2 * tg;
            S[nf][0] *= 0.125f; S[nf][1] *= 0.125f;
            S[nf][2] *= 0.125f; S[nf][3] *= 0.125f;
            if (diag) {
                if (kc0     > q0) S[nf][0] = -1e30f;
                if (kc0 + 1 > q0) S[nf][1] = -1e30f;
                if (kc0     > q1) S[nf][2] = -1e30f;
                if (kc0 + 1 > q1) S[nf][3] = -1e30f;
            }
        }

        // ---- online softmax ----
        float mx0 = -1e30f, mx1 = -1e30f;
#pragma unroll
        for (int nf = 0; nf < 8; nf++) {
            mx0 = fmaxf(mx0, fmaxf(S[nf][0], S[nf][1]));
            mx1 = fmaxf(mx1, fmaxf(S[nf][2], S[nf][3]));
        }
        mx0 = fmaxf(mx0, __shfl_xor_sync(0xffffffffu, mx0, 1));
        mx0 = fmaxf(mx0, __shfl_xor_sync(0xffffffffu, mx0, 2));
        mx1 = fmaxf(mx1, __shfl_xor_sync(0xffffffffu, mx1, 1));
        mx1 = fmaxf(mx1, __shfl_xor_sync(0xffffffffu, mx1, 2));

        float mn0 = fmaxf(m0, mx0), mn1 = fmaxf(m1, mx1);
        float fac0 = __expf(m0 - mn0), fac1 = __expf(m1 - mn1);

        float s0 = 0.f, s1 = 0.f;
#pragma unroll
        for (int nf = 0; nf < 8; nf++) {
            S[nf][0] = __expf(S[nf][0] - mn0);
            S[nf][1] = __expf(S[nf][1] - mn0);
            S[nf][2] = __expf(S[nf][2] - mn1);
            S[nf][3] = __expf(S[nf][3] - mn1);
            s0 += S[nf][0] + S[nf][1];
            s1 += S[nf][2] + S[nf][3];
        }
        s0 += __shfl_xor_sync(0xffffffffu, s0, 1);
        s0 += __shfl_xor_sync(0xffffffffu, s0, 2);
        s1 += __shfl_xor_sync(0xffffffffu, s1, 1);
        s1 += __shfl_xor_sync(0xffffffffu, s1, 2);

        l0 = l0 * fac0 + s0; l1 = l1 * fac1 + s1;
        m0 = mn0; m1 = mn1;
#pragma unroll
        for (int nf = 0; nf < 8; nf++) {
            O[nf][0] *= fac0; O[nf][1] *= fac0;
            O[nf][2] *= fac1; O[nf][3] *= fac1;
        }

        // ---- P -> smem (per-warp rows), then O += P V ----
        {
            int row = warp * 16;
#pragma unroll
            for (int nf = 0; nf < 8; nf++) {
                int col = nf * 8 + 2 * tg;
                Ps[(row + g    ) * PSTR + col    ] = f2tf(S[nf][0]);
                Ps[(row + g    ) * PSTR + col + 1] = f2tf(S[nf][1]);
                Ps[(row + g + 8) * PSTR + col    ] = f2tf(S[nf][2]);
                Ps[(row + g + 8) * PSTR + col + 1] = f2tf(S[nf][3]);
            }
        }
        __syncwarp();

#pragma unroll
        for (int ks = 0; ks < 8; ks++) {
            unsigned a[4];
            int row = warp * 16;
            a[0] = Ps[(row + g    ) * PSTR + ks * 8 + tg    ];
            a[1] = Ps[(row + g + 8) * PSTR + ks * 8 + tg    ];
            a[2] = Ps[(row + g    ) * PSTR + ks * 8 + tg + 4];
            a[3] = Ps[(row + g + 8) * PSTR + ks * 8 + tg + 4];
#pragma unroll
            for (int nf = 0; nf < 8; nf++) {
                unsigned bb[2];
                bb[0] = Vs[(ks * 8 + tg    ) * VSTR + nf * 8 + g];
                bb[1] = Vs[(ks * 8 + tg + 4) * VSTR + nf * 8 + g];
                mma_tf32(O[nf], a, bb);
            }
        }
        __syncwarp();
    }

    // ---- normalize + write (tf32-rounded so O-proj can cp.async) ----
    float inv0 = 1.0f / l0, inv1 = 1.0f / l1;
    float* Ag = g_A + base;
#pragma unroll
    for (int nf = 0; nf < 8; nf++) {
        int col = nf * 8 + 2 * tg;
        float2 o0 = make_float2(__uint_as_float(f2tf(O[nf][0] * inv0)),
                                __uint_as_float(f2tf(O[nf][1] * inv0)));
        float2 o1 = make_float2(__uint_as_float(f2tf(O[nf][2] * inv1)),
                                __uint_as_float(f2tf(O[nf][3] * inv1)));
        *(float2*)(Ag + (size_t)q0 * D_MODEL + col) = o0;
        *(float2*)(Ag + (size_t)q1 * D_MODEL + col) = o1;
    }
}

// ---------------- launch -----------------------------------------------------
extern "C" void kernel_launch(void* const* d_in, const int* in_sizes, int n_in,
                              void* d_out, int out_size)
{
    (void)in_sizes; (void)n_in; (void)out_size;
    const float* in_Q = (const float*)d_in[0];
    const float* in_K = (const float*)d_in[1];
    const float* in_V = (const float*)d_in[2];
    const float* Wq   = (const float*)d_in[3];
    const float* bq   = (const float*)d_in[4];
    const float* Wk   = (const float*)d_in[5];
    const float* bk   = (const float*)d_in[6];
    const float* Wv   = (const float*)d_in[7];
    const float* bv   = (const float*)d_in[8];
    const float* Wo   = (const float*)d_in[9];
    const float* bo   = (const float*)d_in[10];
    float* out = (float*)d_out;

    float *qp, *kp, *vp, *ap;
    float *xq, *xk, *xv, *wq, *wk, *wv, *wo;
    cudaGetSymbolAddress((void**)&qp, g_Q);
    cudaGetSymbolAddress((void**)&kp, g_K);
    cudaGetSymbolAddress((void**)&vp, g_V);
    cudaGetSymbolAddress((void**)&ap, g_A);
    cudaGetSymbolAddress((void**)&xq, g_Xq);
    cudaGetSymbolAddress((void**)&xk, g_Xk);
    cudaGetSymbolAddress((void**)&xv, g_Xv);
    cudaGetSymbolAddress((void**)&wq, g_Wq);
    cudaGetSymbolAddress((void**)&wk, g_Wk);
    cudaGetSymbolAddress((void**)&wv, g_Wv);
    cudaGetSymbolAddress((void**)&wo, g_Wo);

    cudaFuncSetAttribute(gemm_qkv_kernel,
                         cudaFuncAttributeMaxDynamicSharedMemorySize, GEMM_SMEM);
    cudaFuncSetAttribute(gemm_one_kernel,
                         cudaFuncAttributeMaxDynamicSharedMemorySize, GEMM_SMEM);
    cudaFuncSetAttribute(flash_tf32_kernel,
                         cudaFuncAttributeMaxDynamicSharedMemorySize, FLASH_SMEM);

    // 1) pre-round inputs + weights to tf32
    dim3 pr_grid(1024, 1, 7);
    preround_kernel<<<pr_grid, 256>>>(in_Q, in_K, in_V, Wq, Wk, Wv, Wo,
                                      xq, xk, xv, wq, wk, wv, wo);

    // 2) fused QKV projections (outputs tf32-rounded)
    dim3 qkv_grid(D_MODEL / 128, M_TOT / 128, 3);   // (8, 32, 3)
    gemm_qkv_kernel<<<qkv_grid, 256, GEMM_SMEM>>>(
        xq, xk, xv, wq, wk, wv, bq, bk, bv, qp, kp, vp);

    // 3) flash attention (writes tf32-rounded g_A)
    dim3 fgrid(SEQ / 64, BATCH * N_HEADS);          // (32, 32)
    flash_tf32_kernel<<<fgrid, 128, FLASH_SMEM>>>();

    // 4) output projection (fp32 result)
    dim3 o_grid(D_MODEL / 128, M_TOT / 128);        // (8, 32)
    gemm_one_kernel<<<o_grid, 256, GEMM_SMEM>>>(ap, wo, bo, out);
}

// round 13
// speedup vs baseline: 1.4759x; 1.1906x over previous
#include <cuda_runtime.h>
#include <cuda_fp16.h>
#include <math.h>
#include <stdint.h>

// Problem constants
#define D_MODEL 1024
#define N_HEADS 16
#define DKH     64
#define BATCH   2
#define SEQ     2048
#define M_TOT   (BATCH * SEQ)   // 4096

// ---------------- scratch ----------------------------------------------------
__device__ float  g_Q[M_TOT * D_MODEL];     // QKV outputs (tf32-rounded fp32, for flash)
__device__ float  g_K[M_TOT * D_MODEL];
__device__ float  g_V[M_TOT * D_MODEL];
__device__ __half g_Ah[M_TOT * D_MODEL];    // flash output (fp16, for O-proj)
// fp16 copies of inputs and weights
__device__ __half g_Xq[M_TOT * D_MODEL];
__device__ __half g_Xk[M_TOT * D_MODEL];
__device__ __half g_Xv[M_TOT * D_MODEL];
__device__ __half g_Wq[D_MODEL * D_MODEL];
__device__ __half g_Wk[D_MODEL * D_MODEL];
__device__ __half g_Wv[D_MODEL * D_MODEL];
__device__ __half g_Wo[D_MODEL * D_MODEL];

// ---------------- helpers ----------------------------------------------------
__device__ __forceinline__ unsigned f2tf(float f) {
    unsigned r;
    asm("cvt.rna.tf32.f32 %0, %1;" : "=r"(r) : "f"(f));
    return r;
}

__device__ __forceinline__ uint32_t s2u(const void* p) {
    uint32_t a;
    asm("{ .reg .u64 t; cvta.to.shared.u64 t, %1; cvt.u32.u64 %0, t; }"
        : "=r"(a) : "l"(p));
    return a;
}

__device__ __forceinline__ void cpa16(uint32_t s, const void* g) {
    asm volatile("cp.async.cg.shared.global [%0], [%1], 16;" :: "r"(s), "l"(g));
}

__device__ __forceinline__ void mma_tf32(float* c, const unsigned* a, const unsigned* b) {
    asm volatile(
        "mma.sync.aligned.m16n8k8.row.col.f32.tf32.tf32.f32 "
        "{%0,%1,%2,%3}, {%4,%5,%6,%7}, {%8,%9}, {%0,%1,%2,%3};"
        : "+f"(c[0]), "+f"(c[1]), "+f"(c[2]), "+f"(c[3])
        : "r"(a[0]), "r"(a[1]), "r"(a[2]), "r"(a[3]), "r"(b[0]), "r"(b[1]));
}

__device__ __forceinline__ void mma_f16(float* c, const unsigned* a, const unsigned* b) {
    asm volatile(
        "mma.sync.aligned.m16n8k16.row.col.f32.f16.f16.f32 "
        "{%0,%1,%2,%3}, {%4,%5,%6,%7}, {%8,%9}, {%0,%1,%2,%3};"
        : "+f"(c[0]), "+f"(c[1]), "+f"(c[2]), "+f"(c[3])
        : "r"(a[0]), "r"(a[1]), "r"(a[2]), "r"(a[3]), "r"(b[0]), "r"(b[1]));
}

// ---------------- pre-convert pass: fp32 -> fp16 ------------------------------
__global__ __launch_bounds__(256) void preconv_kernel(
    const float* __restrict__ i0, const float* __restrict__ i1, const float* __restrict__ i2,
    const float* __restrict__ w0, const float* __restrict__ w1,
    const float* __restrict__ w2, const float* __restrict__ w3,
    __half* __restrict__ o0, __half* __restrict__ o1, __half* __restrict__ o2,
    __half* __restrict__ o3, __half* __restrict__ o4, __half* __restrict__ o5,
    __half* __restrict__ o6)
{
    const int z = blockIdx.z;
    const float* src;
    __half* dst;
    int n4;
    switch (z) {
        case 0: src = i0; dst = o0; n4 = M_TOT * D_MODEL / 4; break;
        case 1: src = i1; dst = o1; n4 = M_TOT * D_MODEL / 4; break;
        case 2: src = i2; dst = o2; n4 = M_TOT * D_MODEL / 4; break;
        case 3: src = w0; dst = o3; n4 = D_MODEL * D_MODEL / 4; break;
        case 4: src = w1; dst = o4; n4 = D_MODEL * D_MODEL / 4; break;
        case 5: src = w2; dst = o5; n4 = D_MODEL * D_MODEL / 4; break;
        default: src = w3; dst = o6; n4 = D_MODEL * D_MODEL / 4; break;
    }
    const int idx    = blockIdx.x * 256 + threadIdx.x;
    const int stride = gridDim.x * 256;
    for (int i = idx; i < n4; i += stride) {
        float4 v = ((const float4*)src)[i];
        __half2 h0 = __floats2half2_rn(v.x, v.y);
        __half2 h1 = __floats2half2_rn(v.z, v.w);
        uint2 r;
        r.x = *(unsigned*)&h0;
        r.y = *(unsigned*)&h1;
        ((uint2*)dst)[i] = r;
    }
}

// ---------------- GEMM (fp16): Y = X[M,K] * W[N,K]^T + bias ------------------
// 256 thr / 8 warps, CTA tile 128x128, BK=64 (128B fp16 rows), warp tile 64x32.
// cp.async 3-stage pipeline, one barrier per chunk. m16n8k16 fp16 MMA.
#define GSTR      72                         // halves/row (144B): conflict-free frags
#define GSTAGES   3
#define GEMM_KC   64
#define GEMM_NCH  (D_MODEL / GEMM_KC)        // 16 chunks
#define GEMM_BUF  (128 * GSTR)               // halves per operand per stage
#define GEMM_SMEM (2 * GSTAGES * GEMM_BUF * 2)   // 110592 B

template <bool ROUND_OUT>
__device__ __forceinline__ void gemm_body(
    const __half* __restrict__ X, const __half* __restrict__ W,
    const float* __restrict__ bias, float* __restrict__ Y,
    __half* smem)
{
    const int N = D_MODEL, K = D_MODEL;

    __half* Xb[GSTAGES];
    __half* Wb[GSTAGES];
#pragma unroll
    for (int s = 0; s < GSTAGES; s++) {
        Xb[s] = smem + s * GEMM_BUF;
        Wb[s] = smem + (GSTAGES + s) * GEMM_BUF;
    }

    const int tid  = threadIdx.x;
    const int warp = tid >> 5, lane = tid & 31;
    const int wm = warp >> 2, wn = warp & 3;
    const int g  = lane >> 2, tg = lane & 3;
    const int bm = blockIdx.y * 128, bn = blockIdx.x * 128;

    const int lr  = tid >> 1;          // row 0..127
    const int lhs = (tid & 1) * 32;    // half offset 0 / 32

    const __half* xg = X + (size_t)(bm + lr) * K + lhs;
    const __half* wg = W + (size_t)(bn + lr) * K + lhs;
    uint32_t sx[GSTAGES], sw[GSTAGES];
#pragma unroll
    for (int s = 0; s < GSTAGES; s++) {
        sx[s] = s2u(Xb[s] + lr * GSTR + lhs);
        sw[s] = s2u(Wb[s] + lr * GSTR + lhs);
    }

    float c[4][4][4];
#pragma unroll
    for (int mf = 0; mf < 4; mf++)
#pragma unroll
        for (int nf = 0; nf < 4; nf++)
#pragma unroll
            for (int k = 0; k < 4; k++) c[mf][nf][k] = 0.f;

    // stage chunk ch (64 halves of K) into stage buf; ALWAYS commit
    auto issue = [&](int ch, int buf) {
        if (ch < GEMM_NCH) {
            const __half* xp = xg + ch * GEMM_KC;
            const __half* wp = wg + ch * GEMM_KC;
#pragma unroll
            for (int i = 0; i < 4; i++) {
                cpa16(sx[buf] + (uint32_t)(16 * i), xp + 8 * i);
                cpa16(sw[buf] + (uint32_t)(16 * i), wp + 8 * i);
            }
        }
        asm volatile("cp.async.commit_group;" ::: "memory");
    };

    issue(0, 0);
    issue(1, 1);

    for (int ch = 0; ch < GEMM_NCH; ch++) {
        const int buf = ch % GSTAGES;
        asm volatile("cp.async.wait_group 1;" ::: "memory");
        __syncthreads();
        issue(ch + 2, (ch + 2) % GSTAGES);

        const __half* Xs = Xb[buf];
        const __half* Ws = Wb[buf];
#pragma unroll
        for (int ks = 0; ks < 4; ks++) {          // 4 x K16 = K64
            unsigned a[4][4], b[4][2];
            const int kc = ks * 16 + tg * 2;
#pragma unroll
            for (int mf = 0; mf < 4; mf++) {
                int row = wm * 64 + mf * 16;
                a[mf][0] = *(const unsigned*)&Xs[(row + g    ) * GSTR + kc    ];
                a[mf][1] = *(const unsigned*)&Xs[(row + g + 8) * GSTR + kc    ];
                a[mf][2] = *(const unsigned*)&Xs[(row + g    ) * GSTR + kc + 8];
                a[mf][3] = *(const unsigned*)&Xs[(row + g + 8) * GSTR + kc + 8];
            }
#pragma unroll
            for (int nf = 0; nf < 4; nf++) {
                int col = wn * 32 + nf * 8 + g;
                b[nf][0] = *(const unsigned*)&Ws[col * GSTR + kc    ];
                b[nf][1] = *(const unsigned*)&Ws[col * GSTR + kc + 8];
            }
#pragma unroll
            for (int mf = 0; mf < 4; mf++)
#pragma unroll
                for (int nf = 0; nf < 4; nf++)
                    mma_f16(c[mf][nf], a[mf], b[nf]);
        }
    }

    // epilogue: bias + (optional tf32 rounding for flash consumers) + store
#pragma unroll
    for (int mf = 0; mf < 4; mf++) {
#pragma unroll
        for (int nf = 0; nf < 4; nf++) {
            int row = bm + wm * 64 + mf * 16 + g;
            int col = bn + wn * 32 + nf * 8 + 2 * tg;
            float b0 = bias[col], b1 = bias[col + 1];
            float v0 = c[mf][nf][0] + b0, v1 = c[mf][nf][1] + b1;
            float v2 = c[mf][nf][2] + b0, v3 = c[mf][nf][3] + b1;
            if (ROUND_OUT) {
                v0 = __uint_as_float(f2tf(v0)); v1 = __uint_as_float(f2tf(v1));
                v2 = __uint_as_float(f2tf(v2)); v3 = __uint_as_float(f2tf(v3));
            }
            *(float2*)(Y + (size_t)row * N + col)       = make_float2(v0, v1);
            *(float2*)(Y + (size_t)(row + 8) * N + col) = make_float2(v2, v3);
        }
    }
}

// Fused QKV projection: blockIdx.z selects operands; outputs tf32-rounded fp32.
__global__ __launch_bounds__(256, 2)
void gemm_qkv_kernel(const __half* __restrict__ X0, const __half* __restrict__ X1,
                     const __half* __restrict__ X2,
                     const __half* __restrict__ W0, const __half* __restrict__ W1,
                     const __half* __restrict__ W2,
                     const float* __restrict__ b0, const float* __restrict__ b1,
                     const float* __restrict__ b2,
                     float* __restrict__ Y0, float* __restrict__ Y1,
                     float* __restrict__ Y2)
{
    extern __shared__ __half gsm[];
    const int z = blockIdx.z;
    const __half* X = (z == 0) ? X0 : (z == 1) ? X1 : X2;
    const __half* W = (z == 0) ? W0 : (z == 1) ? W1 : W2;
    const float*  B = (z == 0) ? b0 : (z == 1) ? b1 : b2;
    float*        Y = (z == 0) ? Y0 : (z == 1) ? Y1 : Y2;
    gemm_body<true>(X, W, B, Y, gsm);
}

// O-projection: fp32 output (final result).
__global__ __launch_bounds__(256, 2)
void gemm_one_kernel(const __half* __restrict__ X, const __half* __restrict__ W,
                     const float* __restrict__ bias, float* __restrict__ Y)
{
    extern __shared__ __half gsm[];
    gemm_body<false>(X, W, bias, Y, gsm);
}

// ---------------- flash attention, tf32 mma (BQ=64) --------------------------
// 128 thr / 4 warps, 64 q-rows per block, KV tiles of 64.
// g_Q/g_K/g_V are tf32-rounded fp32 -> cp.async staging, NO cvt.
// Output written as fp16 to g_Ah for the fp16 O-projection.
#define PSTR 68   // g-indexed rows: 68 % 32 == 4
#define VSTR 72   // tg-indexed rows: 72 % 32 == 8
#define FLASH_SMEM ((64 * PSTR * 2 + 64 * VSTR) * 4)

__global__ __launch_bounds__(128, 4)
void flash_tf32_kernel()
{
    extern __shared__ unsigned sm[];
    unsigned* Ps = sm;                   // [64][PSTR]  (Q staging, then P)
    unsigned* Ks = Ps + 64 * PSTR;       // [64][PSTR]
    unsigned* Vs = Ks + 64 * PSTR;       // [64][VSTR]

    const int tid  = threadIdx.x;
    const int warp = tid >> 5, lane = tid & 31;
    const int g = lane >> 2, tg = lane & 3;
    const int qt = (int)gridDim.x - 1 - (int)blockIdx.x;   // heavy blocks first
    const int bh = blockIdx.y;
    const int b  = bh >> 4, h = bh & 15;
    const int qbase = qt * 64;

    const size_t base = (size_t)b * SEQ * D_MODEL + (size_t)h * DKH;
    const float* Qg = g_Q + base;
    const float* Kg = g_K + base;
    const float* Vg = g_V + base;

    const int sr = tid >> 4;         // staging row 0..7
    const int sc = (tid & 15) * 4;   // staging col 0..60

    const uint32_t psU = s2u(&Ps[sr * PSTR + sc]);
    const uint32_t ksU = s2u(&Ks[sr * PSTR + sc]);
    const uint32_t vsU = s2u(&Vs[sr * VSTR + sc]);

    // ---- stage Q via cp.async ----
#pragma unroll
    for (int p = 0; p < 8; p++) {
        int r = sr + 8 * p;
        cpa16(psU + (uint32_t)(8 * p * PSTR * 4), Qg + (size_t)(qbase + r) * D_MODEL + sc);
    }
    asm volatile("cp.async.commit_group;" ::: "memory");
    asm volatile("cp.async.wait_group 0;" ::: "memory");
    __syncthreads();

    unsigned qf[8][4];
    {
        int row = warp * 16;
#pragma unroll
        for (int ks = 0; ks < 8; ks++) {
            qf[ks][0] = Ps[(row + g    ) * PSTR + ks * 8 + tg    ];
            qf[ks][1] = Ps[(row + g + 8) * PSTR + ks * 8 + tg    ];
            qf[ks][2] = Ps[(row + g    ) * PSTR + ks * 8 + tg + 4];
            qf[ks][3] = Ps[(row + g + 8) * PSTR + ks * 8 + tg + 4];
        }
    }

    float O[8][4];
#pragma unroll
    for (int nf = 0; nf < 8; nf++)
#pragma unroll
        for (int k = 0; k < 4; k++) O[nf][k] = 0.f;
    float m0 = -1e30f, m1 = -1e30f, l0 = 0.f, l1 = 0.f;

    const int q0 = qbase + warp * 16 + g;
    const int q1 = q0 + 8;

    const int nkt = qt + 1;
    for (int kt = 0; kt < nkt; kt++) {
        const int kbase = kt * 64;
        __syncthreads();
        // ---- stage K,V via cp.async ----
#pragma unroll
        for (int p = 0; p < 8; p++) {
            int r = sr + 8 * p;
            cpa16(ksU + (uint32_t)(8 * p * PSTR * 4), Kg + (size_t)(kbase + r) * D_MODEL + sc);
            cpa16(vsU + (uint32_t)(8 * p * VSTR * 4), Vg + (size_t)(kbase + r) * D_MODEL + sc);
        }
        asm volatile("cp.async.commit_group;" ::: "memory");
        asm volatile("cp.async.wait_group 0;" ::: "memory");
        __syncthreads();

        // ---- S = Q K^T ----
        float S[8][4];
#pragma unroll
        for (int nf = 0; nf < 8; nf++)
#pragma unroll
            for (int k = 0; k < 4; k++) S[nf][k] = 0.f;

#pragma unroll
        for (int ks = 0; ks < 8; ks++) {
#pragma unroll
            for (int nf = 0; nf < 8; nf++) {
                unsigned bb[2];
                bb[0] = Ks[(nf * 8 + g) * PSTR + ks * 8 + tg    ];
                bb[1] = Ks[(nf * 8 + g) * PSTR + ks * 8 + tg + 4];
                mma_tf32(S[nf], qf[ks], bb);
            }
        }

        // ---- scale + causal mask ----
        const bool diag = (kt == qt);
#pragma unroll
        for (int nf = 0; nf < 8; nf++) {
            int kc0 = kbase + nf * 8 + 2 * tg;
            S[nf][0] *= 0.125f; S[nf][1] *= 0.125f;
            S[nf][2] *= 0.125f; S[nf][3] *= 0.125f;
            if (diag) {
                if (kc0     > q0) S[nf][0] = -1e30f;
                if (kc0 + 1 > q0) S[nf][1] = -1e30f;
                if (kc0     > q1) S[nf][2] = -1e30f;
                if (kc0 + 1 > q1) S[nf][3] = -1e30f;
            }
        }

        // ---- online softmax ----
        float mx0 = -1e30f, mx1 = -1e30f;
#pragma unroll
        for (int nf = 0; nf < 8; nf++) {
            mx0 = fmaxf(mx0, fmaxf(S[nf][0], S[nf][1]));
            mx1 = fmaxf(mx1, fmaxf(S[nf][2], S[nf][3]));
        }
        mx0 = fmaxf(mx0, __shfl_xor_sync(0xffffffffu, mx0, 1));
        mx0 = fmaxf(mx0, __shfl_xor_sync(0xffffffffu, mx0, 2));
        mx1 = fmaxf(mx1, __shfl_xor_sync(0xffffffffu, mx1, 1));
        mx1 = fmaxf(mx1, __shfl_xor_sync(0xffffffffu, mx1, 2));

        float mn0 = fmaxf(m0, mx0), mn1 = fmaxf(m1, mx1);
        float fac0 = __expf(m0 - mn0), fac1 = __expf(m1 - mn1);

        float s0 = 0.f, s1 = 0.f;
#pragma unroll
        for (int nf = 0; nf < 8; nf++) {
            S[nf][0] = __expf(S[nf][0] - mn0);
            S[nf][1] = __expf(S[nf][1] - mn0);
            S[nf][2] = __expf(S[nf][2] - mn1);
            S[nf][3] = __expf(S[nf][3] - mn1);
            s0 += S[nf][0] + S[nf][1];
            s1 += S[nf][2] + S[nf][3];
        }
        s0 += __shfl_xor_sync(0xffffffffu, s0, 1);
        s0 += __shfl_xor_sync(0xffffffffu, s0, 2);
        s1 += __shfl_xor_sync(0xffffffffu, s1, 1);
        s1 += __shfl_xor_sync(0xffffffffu, s1, 2);

        l0 = l0 * fac0 + s0; l1 = l1 * fac1 + s1;
        m0 = mn0; m1 = mn1;
#pragma unroll
        for (int nf = 0; nf < 8; nf++) {
            O[nf][0] *= fac0; O[nf][1] *= fac0;
            O[nf][2] *= fac1; O[nf][3] *= fac1;
        }

        // ---- P -> smem (per-warp rows), then O += P V ----
        {
            int row = warp * 16;
#pragma unroll
            for (int nf = 0; nf < 8; nf++) {
                int col = nf * 8 + 2 * tg;
                Ps[(row + g    ) * PSTR + col    ] = f2tf(S[nf][0]);
                Ps[(row + g    ) * PSTR + col + 1] = f2tf(S[nf][1]);
                Ps[(row + g + 8) * PSTR + col    ] = f2tf(S[nf][2]);
                Ps[(row + g + 8) * PSTR + col + 1] = f2tf(S[nf][3]);
            }
        }
        __syncwarp();

#pragma unroll
        for (int ks = 0; ks < 8; ks++) {
            unsigned a[4];
            int row = warp * 16;
            a[0] = Ps[(row + g    ) * PSTR + ks * 8 + tg    ];
            a[1] = Ps[(row + g + 8) * PSTR + ks * 8 + tg    ];
            a[2] = Ps[(row + g    ) * PSTR + ks * 8 + tg + 4];
            a[3] = Ps[(row + g + 8) * PSTR + ks * 8 + tg + 4];
#pragma unroll
            for (int nf = 0; nf < 8; nf++) {
                unsigned bb[2];
                bb[0] = Vs[(ks * 8 + tg    ) * VSTR + nf * 8 + g];
                bb[1] = Vs[(ks * 8 + tg + 4) * VSTR + nf * 8 + g];
                mma_tf32(O[nf], a, bb);
            }
        }
        __syncwarp();
    }

    // ---- normalize + write fp16 (for fp16 O-projection) ----
    float inv0 = 1.0f / l0, inv1 = 1.0f / l1;
    __half* Ag = g_Ah + base;
#pragma unroll
    for (int nf = 0; nf < 8; nf++) {
        int col = nf * 8 + 2 * tg;
        *(__half2*)(Ag + (size_t)q0 * D_MODEL + col) =
            __floats2half2_rn(O[nf][0] * inv0, O[nf][1] * inv0);
        *(__half2*)(Ag + (size_t)q1 * D_MODEL + col) =
            __floats2half2_rn(O[nf][2] * inv1, O[nf][3] * inv1);
    }
}

// ---------------- launch -----------------------------------------------------
extern "C" void kernel_launch(void* const* d_in, const int* in_sizes, int n_in,
                              void* d_out, int out_size)
{
    (void)in_sizes; (void)n_in; (void)out_size;
    const float* in_Q = (const float*)d_in[0];
    const float* in_K = (const float*)d_in[1];
    const float* in_V = (const float*)d_in[2];
    const float* Wq   = (const float*)d_in[3];
    const float* bq   = (const float*)d_in[4];
    const float* Wk   = (const float*)d_in[5];
    const float* bk   = (const float*)d_in[6];
    const float* Wv   = (const float*)d_in[7];
    const float* bv   = (const float*)d_in[8];
    const float* Wo   = (const float*)d_in[9];
    const float* bo   = (const float*)d_in[10];
    float* out = (float*)d_out;

    float *qp, *kp, *vp;
    __half *ah, *xq, *xk, *xv, *wq, *wk, *wv, *wo;
    cudaGetSymbolAddress((void**)&qp, g_Q);
    cudaGetSymbolAddress((void**)&kp, g_K);
    cudaGetSymbolAddress((void**)&vp, g_V);
    cudaGetSymbolAddress((void**)&ah, g_Ah);
    cudaGetSymbolAddress((void**)&xq, g_Xq);
    cudaGetSymbolAddress((void**)&xk, g_Xk);
    cudaGetSymbolAddress((void**)&xv, g_Xv);
    cudaGetSymbolAddress((void**)&wq, g_Wq);
    cudaGetSymbolAddress((void**)&wk, g_Wk);
    cudaGetSymbolAddress((void**)&wv, g_Wv);
    cudaGetSymbolAddress((void**)&wo, g_Wo);

    cudaFuncSetAttribute(gemm_qkv_kernel,
                         cudaFuncAttributeMaxDynamicSharedMemorySize, GEMM_SMEM);
    cudaFuncSetAttribute(gemm_one_kernel,
                         cudaFuncAttributeMaxDynamicSharedMemorySize, GEMM_SMEM);
    cudaFuncSetAttribute(flash_tf32_kernel,
                         cudaFuncAttributeMaxDynamicSharedMemorySize, FLASH_SMEM);

    // 1) convert inputs + weights to fp16
    dim3 pc_grid(1024, 1, 7);
    preconv_kernel<<<pc_grid, 256>>>(in_Q, in_K, in_V, Wq, Wk, Wv, Wo,
                                     xq, xk, xv, wq, wk, wv, wo);

    // 2) fused QKV projections (fp16 mma, tf32-rounded fp32 outputs)
    dim3 qkv_grid(D_MODEL / 128, M_TOT / 128, 3);   // (8, 32, 3)
    gemm_qkv_kernel<<<qkv_grid, 256, GEMM_SMEM>>>(
        xq, xk, xv, wq, wk, wv, bq, bk, bv, qp, kp, vp);

    // 3) flash attention (tf32; writes fp16 g_Ah)
    dim3 fgrid(SEQ / 64, BATCH * N_HEADS);          // (32, 32)
    flash_tf32_kernel<<<fgrid, 128, FLASH_SMEM>>>();

    // 4) output projection (fp16 mma, fp32 result)
    dim3 o_grid(D_MODEL / 128, M_TOT / 128);        // (8, 32)
    gemm_one_kernel<<<o_grid, 256, GEMM_SMEM>>>(ah, wo, bo, out);
}

// round 14
// speedup vs baseline: 1.8057x; 1.2234x over previous
#include <cuda_runtime.h>
#include <cuda_fp16.h>
#include <math.h>
#include <stdint.h>

// Problem constants
#define D_MODEL 1024
#define N_HEADS 16
#define DKH     64
#define BATCH   2
#define SEQ     2048
#define M_TOT   (BATCH * SEQ)   // 4096

// ---------------- scratch ----------------------------------------------------
__device__ __half g_Qh[M_TOT * D_MODEL];    // Q projection (fp16, row-major)
__device__ __half g_Kh[M_TOT * D_MODEL];    // K projection (fp16, row-major)
__device__ __half g_Vt[M_TOT * D_MODEL];    // V projection, per-head transposed: [(b,h,d)][seq]
__device__ __half g_Ah[M_TOT * D_MODEL];    // flash output (fp16, for O-proj)
// fp16 copies of inputs and weights
__device__ __half g_Xq[M_TOT * D_MODEL];
__device__ __half g_Xk[M_TOT * D_MODEL];
__device__ __half g_Xv[M_TOT * D_MODEL];
__device__ __half g_Wq[D_MODEL * D_MODEL];
__device__ __half g_Wk[D_MODEL * D_MODEL];
__device__ __half g_Wv[D_MODEL * D_MODEL];
__device__ __half g_Wo[D_MODEL * D_MODEL];

// ---------------- helpers ----------------------------------------------------
__device__ __forceinline__ uint32_t s2u(const void* p) {
    uint32_t a;
    asm("{ .reg .u64 t; cvta.to.shared.u64 t, %1; cvt.u32.u64 %0, t; }"
        : "=r"(a) : "l"(p));
    return a;
}

__device__ __forceinline__ void cpa16(uint32_t s, const void* g) {
    asm volatile("cp.async.cg.shared.global [%0], [%1], 16;" :: "r"(s), "l"(g));
}

__device__ __forceinline__ void mma_f16(float* c, const unsigned* a, const unsigned* b) {
    asm volatile(
        "mma.sync.aligned.m16n8k16.row.col.f32.f16.f16.f32 "
        "{%0,%1,%2,%3}, {%4,%5,%6,%7}, {%8,%9}, {%0,%1,%2,%3};"
        : "+f"(c[0]), "+f"(c[1]), "+f"(c[2]), "+f"(c[3])
        : "r"(a[0]), "r"(a[1]), "r"(a[2]), "r"(a[3]), "r"(b[0]), "r"(b[1]));
}

// ---------------- pre-convert pass: fp32 -> fp16 ------------------------------
__global__ __launch_bounds__(256) void preconv_kernel(
    const float* __restrict__ i0, const float* __restrict__ i1, const float* __restrict__ i2,
    const float* __restrict__ w0, const float* __restrict__ w1,
    const float* __restrict__ w2, const float* __restrict__ w3,
    __half* __restrict__ o0, __half* __restrict__ o1, __half* __restrict__ o2,
    __half* __restrict__ o3, __half* __restrict__ o4, __half* __restrict__ o5,
    __half* __restrict__ o6)
{
    const int z = blockIdx.z;
    const float* src;
    __half* dst;
    int n4;
    switch (z) {
        case 0: src = i0; dst = o0; n4 = M_TOT * D_MODEL / 4; break;
        case 1: src = i1; dst = o1; n4 = M_TOT * D_MODEL / 4; break;
        case 2: src = i2; dst = o2; n4 = M_TOT * D_MODEL / 4; break;
        case 3: src = w0; dst = o3; n4 = D_MODEL * D_MODEL / 4; break;
        case 4: src = w1; dst = o4; n4 = D_MODEL * D_MODEL / 4; break;
        case 5: src = w2; dst = o5; n4 = D_MODEL * D_MODEL / 4; break;
        default: src = w3; dst = o6; n4 = D_MODEL * D_MODEL / 4; break;
    }
    const int idx    = blockIdx.x * 256 + threadIdx.x;
    const int stride = gridDim.x * 256;
    for (int i = idx; i < n4; i += stride) {
        float4 v = ((const float4*)src)[i];
        __half2 h0 = __floats2half2_rn(v.x, v.y);
        __half2 h1 = __floats2half2_rn(v.z, v.w);
        uint2 r;
        r.x = *(unsigned*)&h0;
        r.y = *(unsigned*)&h1;
        ((uint2*)dst)[i] = r;
    }
}

// ---------------- GEMM (fp16): Y = X[M,K] * W[N,K]^T + bias ------------------
// 256 thr / 8 warps, CTA tile 128x128, BK=64, warp tile 64x32.
// cp.async 3-stage pipeline. OUT_MODE: 0 = fp32 row-major, 1 = fp16 row-major,
// 2 = fp16 per-head-transposed (for V -> g_Vt).
#define GSTR      72
#define GSTAGES   3
#define GEMM_KC   64
#define GEMM_NCH  (D_MODEL / GEMM_KC)        // 16 chunks
#define GEMM_BUF  (128 * GSTR)
#define GEMM_SMEM (2 * GSTAGES * GEMM_BUF * 2)   // 110592 B

template <int OUT_MODE>
__device__ __forceinline__ void gemm_body(
    const __half* __restrict__ X, const __half* __restrict__ W,
    const float* __restrict__ bias, void* __restrict__ Yv,
    __half* smem)
{
    const int N = D_MODEL, K = D_MODEL;

    __half* Xb[GSTAGES];
    __half* Wb[GSTAGES];
#pragma unroll
    for (int s = 0; s < GSTAGES; s++) {
        Xb[s] = smem + s * GEMM_BUF;
        Wb[s] = smem + (GSTAGES + s) * GEMM_BUF;
    }

    const int tid  = threadIdx.x;
    const int warp = tid >> 5, lane = tid & 31;
    const int wm = warp >> 2, wn = warp & 3;
    const int g  = lane >> 2, tg = lane & 3;
    const int bm = blockIdx.y * 128, bn = blockIdx.x * 128;

    const int lr  = tid >> 1;
    const int lhs = (tid & 1) * 32;

    const __half* xg = X + (size_t)(bm + lr) * K + lhs;
    const __half* wg = W + (size_t)(bn + lr) * K + lhs;
    uint32_t sx[GSTAGES], sw[GSTAGES];
#pragma unroll
    for (int s = 0; s < GSTAGES; s++) {
        sx[s] = s2u(Xb[s] + lr * GSTR + lhs);
        sw[s] = s2u(Wb[s] + lr * GSTR + lhs);
    }

    float c[4][4][4];
#pragma unroll
    for (int mf = 0; mf < 4; mf++)
#pragma unroll
        for (int nf = 0; nf < 4; nf++)
#pragma unroll
            for (int k = 0; k < 4; k++) c[mf][nf][k] = 0.f;

    auto issue = [&](int ch, int buf) {
        if (ch < GEMM_NCH) {
            const __half* xp = xg + ch * GEMM_KC;
            const __half* wp = wg + ch * GEMM_KC;
#pragma unroll
            for (int i = 0; i < 4; i++) {
                cpa16(sx[buf] + (uint32_t)(16 * i), xp + 8 * i);
                cpa16(sw[buf] + (uint32_t)(16 * i), wp + 8 * i);
            }
        }
        asm volatile("cp.async.commit_group;" ::: "memory");
    };

    issue(0, 0);
    issue(1, 1);

    for (int ch = 0; ch < GEMM_NCH; ch++) {
        const int buf = ch % GSTAGES;
        asm volatile("cp.async.wait_group 1;" ::: "memory");
        __syncthreads();
        issue(ch + 2, (ch + 2) % GSTAGES);

        const __half* Xs = Xb[buf];
        const __half* Ws = Wb[buf];
#pragma unroll
        for (int ks = 0; ks < 4; ks++) {
            unsigned a[4][4], b[4][2];
            const int kc = ks * 16 + tg * 2;
#pragma unroll
            for (int mf = 0; mf < 4; mf++) {
                int row = wm * 64 + mf * 16;
                a[mf][0] = *(const unsigned*)&Xs[(row + g    ) * GSTR + kc    ];
                a[mf][1] = *(const unsigned*)&Xs[(row + g + 8) * GSTR + kc    ];
                a[mf][2] = *(const unsigned*)&Xs[(row + g    ) * GSTR + kc + 8];
                a[mf][3] = *(const unsigned*)&Xs[(row + g + 8) * GSTR + kc + 8];
            }
#pragma unroll
            for (int nf = 0; nf < 4; nf++) {
                int col = wn * 32 + nf * 8 + g;
                b[nf][0] = *(const unsigned*)&Ws[col * GSTR + kc    ];
                b[nf][1] = *(const unsigned*)&Ws[col * GSTR + kc + 8];
            }
#pragma unroll
            for (int mf = 0; mf < 4; mf++)
#pragma unroll
                for (int nf = 0; nf < 4; nf++)
                    mma_f16(c[mf][nf], a[mf], b[nf]);
        }
    }

    // epilogue
#pragma unroll
    for (int mf = 0; mf < 4; mf++) {
#pragma unroll
        for (int nf = 0; nf < 4; nf++) {
            int row = bm + wm * 64 + mf * 16 + g;
            int col = bn + wn * 32 + nf * 8 + 2 * tg;
            float b0 = bias[col], b1 = bias[col + 1];
            float v0 = c[mf][nf][0] + b0, v1 = c[mf][nf][1] + b1;
            float v2 = c[mf][nf][2] + b0, v3 = c[mf][nf][3] + b1;
            if (OUT_MODE == 0) {
                float* Y = (float*)Yv;
                *(float2*)(Y + (size_t)row * N + col)       = make_float2(v0, v1);
                *(float2*)(Y + (size_t)(row + 8) * N + col) = make_float2(v2, v3);
            } else if (OUT_MODE == 1) {
                __half* Y = (__half*)Yv;
                *(__half2*)(Y + (size_t)row * N + col)       = __floats2half2_rn(v0, v1);
                *(__half2*)(Y + (size_t)(row + 8) * N + col) = __floats2half2_rn(v2, v3);
            } else {
                // per-head transpose: Yt[((b*16+h)*64 + d)][s]
                __half* Y = (__half*)Yv;
                int bb = row >> 11, s = row & (SEQ - 1);
                int h  = col >> 6,  d = col & 63;
                size_t r0 = ((size_t)(bb * N_HEADS + h) * DKH + d) * SEQ;
                Y[r0 + s]            = __float2half_rn(v0);
                Y[r0 + SEQ + s]      = __float2half_rn(v1);   // d+1
                Y[r0 + s + 8]        = __float2half_rn(v2);
                Y[r0 + SEQ + s + 8]  = __float2half_rn(v3);
            }
        }
    }
}

// Fused QKV projection: z=0 -> Q (fp16), z=1 -> K (fp16), z=2 -> V (fp16 transposed)
__global__ __launch_bounds__(256, 2)
void gemm_qkv_kernel(const __half* __restrict__ X0, const __half* __restrict__ X1,
                     const __half* __restrict__ X2,
                     const __half* __restrict__ W0, const __half* __restrict__ W1,
                     const __half* __restrict__ W2,
                     const float* __restrict__ b0, const float* __restrict__ b1,
                     const float* __restrict__ b2,
                     __half* __restrict__ Y0, __half* __restrict__ Y1,
                     __half* __restrict__ Y2)
{
    extern __shared__ __half gsm[];
    const int z = blockIdx.z;
    if (z == 2) {
        gemm_body<2>(X2, W2, b2, Y2, gsm);
    } else if (z == 1) {
        gemm_body<1>(X1, W1, b1, Y1, gsm);
    } else {
        gemm_body<1>(X0, W0, b0, Y0, gsm);
    }
}

// O-projection: fp32 output (final result).
__global__ __launch_bounds__(256, 2)
void gemm_one_kernel(const __half* __restrict__ X, const __half* __restrict__ W,
                     const float* __restrict__ bias, float* __restrict__ Y)
{
    extern __shared__ __half gsm[];
    gemm_body<0>(X, W, bias, Y, gsm);
}

// ---------------- flash attention, fp16 mma (BQ=64) --------------------------
// 128 thr / 4 warps, 64 q-rows per block, KV tiles of 64. All operands fp16,
// accumulate fp32. V comes pre-transposed (g_Vt) so PV B-frags are LDS.32.
#define PSTRH 72   // halves per row
#define KSTRH 72
#define VSTRH 72
#define FLASH_SMEM ((64 * PSTRH + 64 * KSTRH + 64 * VSTRH) * 2)   // 27648 B

__global__ __launch_bounds__(128, 4)
void flash_f16_kernel()
{
    extern __shared__ __half fsm[];
    __half* Ph  = fsm;                    // [64][PSTRH]  Q staging, then P
    __half* Kh  = Ph + 64 * PSTRH;        // [64][KSTRH]  K tile (row=key, col=d)
    __half* Vth = Kh + 64 * KSTRH;        // [64][VSTRH]  Vt tile (row=d, col=key)

    const int tid  = threadIdx.x;
    const int warp = tid >> 5, lane = tid & 31;
    const int g = lane >> 2, tg = lane & 3;
    const int qt = (int)gridDim.x - 1 - (int)blockIdx.x;   // heavy blocks first
    const int bh = blockIdx.y;
    const int b  = bh >> 4, h = bh & 15;
    const int qbase = qt * 64;
    const int row0  = warp * 16;

    const size_t base  = (size_t)b * SEQ * D_MODEL + (size_t)h * DKH;
    const __half* Qg  = g_Qh + base;
    const __half* Kg  = g_Kh + base;
    const __half* Vtg = g_Vt + (size_t)(b * N_HEADS + h) * DKH * SEQ;

    const int sr = tid >> 3;          // staging row 0..15
    const int sc = (tid & 7) * 8;     // staging col (halves) 0..56

    const uint32_t phU = s2u(&Ph[sr * PSTRH + sc]);
    const uint32_t khU = s2u(&Kh[sr * KSTRH + sc]);
    const uint32_t vtU = s2u(&Vth[sr * VSTRH + sc]);

    // ---- stage Q via cp.async ----
#pragma unroll
    for (int p = 0; p < 4; p++) {
        int r = sr + 16 * p;
        cpa16(phU + (uint32_t)(16 * p * PSTRH * 2), Qg + (size_t)(qbase + r) * D_MODEL + sc);
    }
    asm volatile("cp.async.commit_group;" ::: "memory");
    asm volatile("cp.async.wait_group 0;" ::: "memory");
    __syncthreads();

    // ---- extract Q fragments (warp's 16 rows) ----
    unsigned qf[4][4];
#pragma unroll
    for (int ks = 0; ks < 4; ks++) {
        const int kc = ks * 16 + tg * 2;
        qf[ks][0] = *(const unsigned*)&Ph[(row0 + g    ) * PSTRH + kc    ];
        qf[ks][1] = *(const unsigned*)&Ph[(row0 + g + 8) * PSTRH + kc    ];
        qf[ks][2] = *(const unsigned*)&Ph[(row0 + g    ) * PSTRH + kc + 8];
        qf[ks][3] = *(const unsigned*)&Ph[(row0 + g + 8) * PSTRH + kc + 8];
    }

    float O[8][4];
#pragma unroll
    for (int nf = 0; nf < 8; nf++)
#pragma unroll
        for (int k = 0; k < 4; k++) O[nf][k] = 0.f;
    float m0 = -1e30f, m1 = -1e30f, l0 = 0.f, l1 = 0.f;

    const int q0 = qbase + row0 + g;
    const int q1 = q0 + 8;

    const int nkt = qt + 1;
    for (int kt = 0; kt < nkt; kt++) {
        const int kbase = kt * 64;
        __syncthreads();
        // ---- stage K (row-major) and Vt (d-major) via cp.async ----
#pragma unroll
        for (int p = 0; p < 4; p++) {
            int r = sr + 16 * p;
            cpa16(khU + (uint32_t)(16 * p * KSTRH * 2), Kg + (size_t)(kbase + r) * D_MODEL + sc);
            cpa16(vtU + (uint32_t)(16 * p * VSTRH * 2), Vtg + (size_t)r * SEQ + kbase + sc);
        }
        asm volatile("cp.async.commit_group;" ::: "memory");
        asm volatile("cp.async.wait_group 0;" ::: "memory");
        __syncthreads();

        // ---- S = Q K^T  (m16 x n64, fp16) ----
        float S[8][4];
#pragma unroll
        for (int nf = 0; nf < 8; nf++)
#pragma unroll
            for (int k = 0; k < 4; k++) S[nf][k] = 0.f;

#pragma unroll
        for (int ks = 0; ks < 4; ks++) {
            const int kc = ks * 16 + tg * 2;
#pragma unroll
            for (int nf = 0; nf < 8; nf++) {
                unsigned bb[2];
                bb[0] = *(const unsigned*)&Kh[(nf * 8 + g) * KSTRH + kc    ];
                bb[1] = *(const unsigned*)&Kh[(nf * 8 + g) * KSTRH + kc + 8];
                mma_f16(S[nf], qf[ks], bb);
            }
        }

        // ---- scale + causal mask ----
        const bool diag = (kt == qt);
#pragma unroll
        for (int nf = 0; nf < 8; nf++) {
            int kc0 = kbase + nf * 8 + 2 * tg;
            S[nf][0] *= 0.125f; S[nf][1] *= 0.125f;
            S[nf][2] *= 0.125f; S[nf][3] *= 0.125f;
            if (diag) {
                if (kc0     > q0) S[nf][0] = -1e30f;
                if (kc0 + 1 > q0) S[nf][1] = -1e30f;
                if (kc0     > q1) S[nf][2] = -1e30f;
                if (kc0 + 1 > q1) S[nf][3] = -1e30f;
            }
        }

        // ---- online softmax ----
        float mx0 = -1e30f, mx1 = -1e30f;
#pragma unroll
        for (int nf = 0; nf < 8; nf++) {
            mx0 = fmaxf(mx0, fmaxf(S[nf][0], S[nf][1]));
            mx1 = fmaxf(mx1, fmaxf(S[nf][2], S[nf][3]));
        }
        mx0 = fmaxf(mx0, __shfl_xor_sync(0xffffffffu, mx0, 1));
        mx0 = fmaxf(mx0, __shfl_xor_sync(0xffffffffu, mx0, 2));
        mx1 = fmaxf(mx1, __shfl_xor_sync(0xffffffffu, mx1, 1));
        mx1 = fmaxf(mx1, __shfl_xor_sync(0xffffffffu, mx1, 2));

        float mn0 = fmaxf(m0, mx0), mn1 = fmaxf(m1, mx1);
        float fac0 = __expf(m0 - mn0), fac1 = __expf(m1 - mn1);

        float s0 = 0.f, s1 = 0.f;
#pragma unroll
        for (int nf = 0; nf < 8; nf++) {
            S[nf][0] = __expf(S[nf][0] - mn0);
            S[nf][1] = __expf(S[nf][1] - mn0);
            S[nf][2] = __expf(S[nf][2] - mn1);
            S[nf][3] = __expf(S[nf][3] - mn1);
            s0 += S[nf][0] + S[nf][1];
            s1 += S[nf][2] + S[nf][3];
        }
        s0 += __shfl_xor_sync(0xffffffffu, s0, 1);
        s0 += __shfl_xor_sync(0xffffffffu, s0, 2);
        s1 += __shfl_xor_sync(0xffffffffu, s1, 1);
        s1 += __shfl_xor_sync(0xffffffffu, s1, 2);

        l0 = l0 * fac0 + s0; l1 = l1 * fac1 + s1;
        m0 = mn0; m1 = mn1;
#pragma unroll
        for (int nf = 0; nf < 8; nf++) {
            O[nf][0] *= fac0; O[nf][1] *= fac0;
            O[nf][2] *= fac1; O[nf][3] *= fac1;
        }

        // ---- P -> smem fp16 (per-warp rows) ----
#pragma unroll
        for (int nf = 0; nf < 8; nf++) {
            int col = nf * 8 + 2 * tg;
            *(__half2*)&Ph[(row0 + g    ) * PSTRH + col] = __floats2half2_rn(S[nf][0], S[nf][1]);
            *(__half2*)&Ph[(row0 + g + 8) * PSTRH + col] = __floats2half2_rn(S[nf][2], S[nf][3]);
        }
        __syncwarp();

        // ---- O += P V  (fp16: A=P row-major, B=Vt d-major) ----
#pragma unroll
        for (int ks = 0; ks < 4; ks++) {
            const int kc = ks * 16 + tg * 2;
            unsigned a[4];
            a[0] = *(const unsigned*)&Ph[(row0 + g    ) * PSTRH + kc    ];
            a[1] = *(const unsigned*)&Ph[(row0 + g + 8) * PSTRH + kc    ];
            a[2] = *(const unsigned*)&Ph[(row0 + g    ) * PSTRH + kc + 8];
            a[3] = *(const unsigned*)&Ph[(row0 + g + 8) * PSTRH + kc + 8];
#pragma unroll
            for (int nf = 0; nf < 8; nf++) {
                unsigned bb[2];
                bb[0] = *(const unsigned*)&Vth[(nf * 8 + g) * VSTRH + kc    ];
                bb[1] = *(const unsigned*)&Vth[(nf * 8 + g) * VSTRH + kc + 8];
                mma_f16(O[nf], a, bb);
            }
        }
        __syncwarp();
    }

    // ---- normalize + write fp16 ----
    float inv0 = 1.0f / l0, inv1 = 1.0f / l1;
    __half* Ag = g_Ah + base;
#pragma unroll
    for (int nf = 0; nf < 8; nf++) {
        int col = nf * 8 + 2 * tg;
        *(__half2*)(Ag + (size_t)q0 * D_MODEL + col) =
            __floats2half2_rn(O[nf][0] * inv0, O[nf][1] * inv0);
        *(__half2*)(Ag + (size_t)q1 * D_MODEL + col) =
            __floats2half2_rn(O[nf][2] * inv1, O[nf][3] * inv1);
    }
}

// ---------------- launch -----------------------------------------------------
extern "C" void kernel_launch(void* const* d_in, const int* in_sizes, int n_in,
                              void* d_out, int out_size)
{
    (void)in_sizes; (void)n_in; (void)out_size;
    const float* in_Q = (const float*)d_in[0];
    const float* in_K = (const float*)d_in[1];
    const float* in_V = (const float*)d_in[2];
    const float* Wq   = (const float*)d_in[3];
    const float* bq   = (const float*)d_in[4];
    const float* Wk   = (const float*)d_in[5];
    const float* bk   = (const float*)d_in[6];
    const float* Wv   = (const float*)d_in[7];
    const float* bv   = (const float*)d_in[8];
    const float* Wo   = (const float*)d_in[9];
    const float* bo   = (const float*)d_in[10];
    float* out = (float*)d_out;

    __half *qh, *kh, *vt, *ah, *xq, *xk, *xv, *wq, *wk, *wv, *wo;
    cudaGetSymbolAddress((void**)&qh, g_Qh);
    cudaGetSymbolAddress((void**)&kh, g_Kh);
    cudaGetSymbolAddress((void**)&vt, g_Vt);
    cudaGetSymbolAddress((void**)&ah, g_Ah);
    cudaGetSymbolAddress((void**)&xq, g_Xq);
    cudaGetSymbolAddress((void**)&xk, g_Xk);
    cudaGetSymbolAddress((void**)&xv, g_Xv);
    cudaGetSymbolAddress((void**)&wq, g_Wq);
    cudaGetSymbolAddress((void**)&wk, g_Wk);
    cudaGetSymbolAddress((void**)&wv, g_Wv);
    cudaGetSymbolAddress((void**)&wo, g_Wo);

    cudaFuncSetAttribute(gemm_qkv_kernel,
                         cudaFuncAttributeMaxDynamicSharedMemorySize, GEMM_SMEM);
    cudaFuncSetAttribute(gemm_one_kernel,
                         cudaFuncAttributeMaxDynamicSharedMemorySize, GEMM_SMEM);
    cudaFuncSetAttribute(flash_f16_kernel,
                         cudaFuncAttributeMaxDynamicSharedMemorySize, FLASH_SMEM);

    // 1) convert inputs + weights to fp16
    dim3 pc_grid(1024, 1, 7);
    preconv_kernel<<<pc_grid, 256>>>(in_Q, in_K, in_V, Wq, Wk, Wv, Wo,
                                     xq, xk, xv, wq, wk, wv, wo);

    // 2) fused QKV projections (fp16 outputs; V transposed per head)
    dim3 qkv_grid(D_MODEL / 128, M_TOT / 128, 3);   // (8, 32, 3)
    gemm_qkv_kernel<<<qkv_grid, 256, GEMM_SMEM>>>(
        xq, xk, xv, wq, wk, wv, bq, bk, bv, qh, kh, vt);

    // 3) flash attention (fp16; writes fp16 g_Ah)
    dim3 fgrid(SEQ / 64, BATCH * N_HEADS);          // (32, 32)
    flash_f16_kernel<<<fgrid, 128, FLASH_SMEM>>>();

    // 4) output projection (fp16 mma, fp32 result)
    dim3 o_grid(D_MODEL / 128, M_TOT / 128);        // (8, 32)
    gemm_one_kernel<<<o_grid, 256, GEMM_SMEM>>>(ah, wo, bo, out);
}